// round 6
// baseline (speedup 1.0000x reference)
#include <cuda_runtime.h>
#include <cuda_bf16.h>
#include <cstdint>

// ===========================================================================
// Fused Goal_Conditioned_Policies forward, warp-MMA (HMMA bf16) conv2.
// One CTA per sample (B=4096), 512 threads (16 warps), 1 CTA/SM.
//   conv1 (FFMA fp32, lane=oc, weights in regs) -> P: parity-split NHWC bf16
//   conv2 = GEMM D[256 pos][64 oc] = im2col(P) @ w2^T via mma.sync m16n8k16
//     5 K-chunks of 64 (tap pairs); 1 m-tile per warp; bias-init accumulators;
//     relu+meanpool from fragments.
//   MLP (fp32, K-split + shfl reduce) -> warp-parallel softmax
// ===========================================================================

#define NTHREADS 512
#define NVAR     50

// ---- smem byte offsets ----
#define P_OFF    0u            // parity NHWC h1: [2][2][4 icg][17][17][16 B] = 73,984
#define XP_OFF   73984u        // x padded fp32 [3][66][68] = 53,856
#define A_OFF    73984u        // A chunk [256 rows][144 B] = 36,864 (aliases XP)
#define B2W_OFF  127840u       // B weights [320 k][144 B] = 46,080
#define CS_OFF   173920u       // C[b] 50x50 fp32 = 10,000
#define W1S_OFF  183920u       // conv1 weights 864 fp32 = 3,456
#define VEC_OFF  187376u       // small vectors (floats below)
#define SMEM_BYTES 194576u

// vec float indices
#define V_B2S  0
#define V_PP   64        // pool partials [16 warps][64]
#define V_POOL 1088
#define V_X1   1152
#define V_X2   1280
#define V_E    1344
#define V_X3   1408
#define V_X5   1536
#define V_X6   1600
#define V_X7   1664
#define V_LG   1728
#define V_RED  1792

__device__ __forceinline__ uint32_t smem_u32(const void* p) {
    uint32_t a;
    asm("{ .reg .u64 t; cvta.to.shared.u64 t, %1; cvt.u32.u64 %0, t; }" : "=r"(a) : "l"(p));
    return a;
}
__device__ __forceinline__ void ldsm_x4(uint32_t* r, uint32_t addr) {
    asm volatile("ldmatrix.sync.aligned.m8n8.x4.shared.b16 {%0,%1,%2,%3}, [%4];"
        : "=r"(r[0]), "=r"(r[1]), "=r"(r[2]), "=r"(r[3]) : "r"(addr));
}
__device__ __forceinline__ void ldsm_x4_t(uint32_t* r, uint32_t addr) {
    asm volatile("ldmatrix.sync.aligned.m8n8.x4.trans.shared.b16 {%0,%1,%2,%3}, [%4];"
        : "=r"(r[0]), "=r"(r[1]), "=r"(r[2]), "=r"(r[3]) : "r"(addr));
}
__device__ __forceinline__ void mma16816(float* d, const uint32_t* a, const uint32_t* b) {
    asm volatile(
        "mma.sync.aligned.m16n8k16.row.col.f32.bf16.bf16.f32 "
        "{%0,%1,%2,%3}, {%4,%5,%6,%7}, {%8,%9}, {%0,%1,%2,%3};"
        : "+f"(d[0]), "+f"(d[1]), "+f"(d[2]), "+f"(d[3])
        : "r"(a[0]), "r"(a[1]), "r"(a[2]), "r"(a[3]), "r"(b[0]), "r"(b[1]));
}

// B weights bf16, k-major [kk][oc], row padded to 144 B. kk = c*64 + parity*32 + ic.
__device__ __align__(16) __nv_bfloat16 g_B2[320 * 72];

__global__ void b_prep_kernel(const float* __restrict__ w2) {
    int i = blockIdx.x * blockDim.x + threadIdx.x;   // 320*64 = 20480
    if (i >= 320 * 64) return;
    int kk = i >> 6, oc = i & 63;
    int c = kk >> 6, rem = kk & 63;
    int tap = 2 * c + (rem >> 5);
    int ic  = rem & 31;
    float v = (tap < 9) ? w2[(oc * 32 + ic) * 9 + tap] : 0.f;
    g_B2[kk * 72 + oc] = __float2bfloat16(v);
}

__global__ __launch_bounds__(NTHREADS, 1)
void gcp_tc_kernel(const float* __restrict__ x,    const float* __restrict__ C,
                   const float* __restrict__ w1,   const float* __restrict__ b1,
                   const float* __restrict__ b2,
                   const float* __restrict__ encw, const float* __restrict__ encb,
                   const float* __restrict__ f1w,  const float* __restrict__ f1b,
                   const float* __restrict__ f2w,  const float* __restrict__ f2b,
                   const float* __restrict__ f3w,  const float* __restrict__ f3b,
                   const float* __restrict__ f4w,  const float* __restrict__ f4b,
                   const float* __restrict__ f5w,  const float* __restrict__ f5b,
                   const float* __restrict__ ow,   const float* __restrict__ ob,
                   float* __restrict__ out)
{
    extern __shared__ char smc[];
    const uint32_t smaddr = smem_u32(smc);
    const int b    = blockIdx.x;
    const int tid  = threadIdx.x;
    const int wrp  = tid >> 5;
    const int lane = tid & 31;
    float* vec = (float*)(smc + VEC_OFF);

    // ---- stage: zero P+XP (pads must be 0), load B weights, w1, b2, C ----
    {
        uint4 z = make_uint4(0, 0, 0, 0);
        for (int i = tid; i < 7990; i += NTHREADS)      // (P + XP) / 16
            ((uint4*)(smc + P_OFF))[i] = z;
        const uint4* gb = (const uint4*)g_B2;
        for (int i = tid; i < 2880; i += NTHREADS)      // 46080/16
            ((uint4*)(smc + B2W_OFF))[i] = gb[i];
        float* w1s = (float*)(smc + W1S_OFF);
        for (int i = tid; i < 864; i += NTHREADS) w1s[i] = w1[i];
        if (tid < 64) vec[V_B2S + tid] = b2[tid];
        float* cs = (float*)(smc + CS_OFF);
        for (int i = tid; i < 2500; i += NTHREADS) cs[i] = C[b * 2500 + i];
    }
    __syncthreads();

    // ---- x interior into padded [3][66][68] fp32 ----
    {
        float* xp = (float*)(smc + XP_OFF);
        const float4* xg = (const float4*)(x + (size_t)b * 12288);
        for (int i = tid; i < 3072; i += NTHREADS) {
            int ic  = i >> 10;
            int rem = i & 1023;
            int row = rem >> 4;
            int c4  = rem & 15;
            float4 v = xg[i];
            float* d = xp + (ic * 66 + row + 1) * 68 + c4 * 4 + 1;
            d[0] = v.x; d[1] = v.y; d[2] = v.z; d[3] = v.w;
        }
    }
    __syncthreads();

    // =====================================================================
    // conv1: lane = oc (0..31), weights in registers, 2x2 output quads.
    // 16 warps x 16 quads. Writes P parity-split NHWC bf16.
    // =====================================================================
    {
        float wreg[27];
        {
            const float* w1s = (const float*)(smc + W1S_OFF);
            #pragma unroll
            for (int j = 0; j < 27; j++) wreg[j] = w1s[lane * 27 + j];
        }
        const float breg = b1[lane];
        const float* xp = (const float*)(smc + XP_OFF);

        for (int q = wrp; q < 256; q += 16) {
            int Y = q >> 4, X = q & 15;
            float a00 = breg, a01 = breg, a10 = breg, a11 = breg;
            #pragma unroll
            for (int ic = 0; ic < 3; ic++) {
                const float* base = xp + (ic * 66 + 4 * Y) * 68 + 4 * X;
                float xv[5][5];
                #pragma unroll
                for (int i = 0; i < 5; i++) {
                    float4 v = *(const float4*)(base + i * 68);
                    xv[i][0] = v.x; xv[i][1] = v.y; xv[i][2] = v.z; xv[i][3] = v.w;
                    xv[i][4] = base[i * 68 + 4];
                }
                #pragma unroll
                for (int ky = 0; ky < 3; ky++)
                    #pragma unroll
                    for (int kx = 0; kx < 3; kx++) {
                        float w = wreg[ic * 9 + ky * 3 + kx];
                        a00 = fmaf(xv[ky][kx],         w, a00);
                        a01 = fmaf(xv[ky][2 + kx],     w, a01);
                        a10 = fmaf(xv[2 + ky][kx],     w, a10);
                        a11 = fmaf(xv[2 + ky][2 + kx], w, a11);
                    }
            }
            const int g  = lane >> 3;
            const int lo = (lane & 7) * 2;
            #pragma unroll
            for (int a = 0; a < 2; a++)
                #pragma unroll
                for (int bb = 0; bb < 2; bb++) {
                    int y  = 2 * Y + a,  xx = 2 * X + bb;
                    int py = (y + 1) & 1, iy = (y + 1) >> 1;
                    int px = (xx + 1) & 1, ix = (xx + 1) >> 1;
                    float v = (a == 0) ? (bb == 0 ? a00 : a01) : (bb == 0 ? a10 : a11);
                    uint32_t off = P_OFF +
                        (uint32_t)(((((py * 2 + px) * 4 + g) * 17 + iy) * 17) + ix) * 16u + lo;
                    *(__nv_bfloat16*)(smc + off) = __float2bfloat16(fmaxf(v, 0.f));
                }
        }
    }

    // =====================================================================
    // conv2 GEMM: acc[8 n-tiles][4], bias-initialized. 1 m-tile per warp.
    // 5 chunks of K=64 (tap pairs); A chunk rebuilt per chunk (aliases XP);
    // A rows built by 2 threads each (one tap-pair half per thread).
    // =====================================================================
    float acc[8][4];
    {
        const int cB = (lane & 3) * 2;
        #pragma unroll
        for (int j = 0; j < 8; j++) {
            float b0  = vec[V_B2S + j * 8 + cB];
            float b1v = vec[V_B2S + j * 8 + cB + 1];
            acc[j][0] = b0;  acc[j][1] = b1v;
            acc[j][2] = b0;  acc[j][3] = b1v;
        }
    }
    {
        const int r = tid >> 1, part = tid & 1;
        const int oy = r >> 4, ox = r & 15;
        char* dst = smc + A_OFF + (uint32_t)r * 144u + (uint32_t)part * 64u;
        const uint32_t a_lane_base = smaddr + A_OFF
                                     + (uint32_t)(wrp * 16 + (lane & 15)) * 144u
                                     + (uint32_t)(lane >> 4) * 16u;
        const uint32_t b_lane_base = smaddr + B2W_OFF + (uint32_t)(lane & 15) * 144u
                                     + (uint32_t)(lane >> 4) * 16u;

        for (int c = 0; c < 5; c++) {
            __syncthreads();   // conv1 done (c=0) / prior chunk ldsm reads done
            // ---- build A half-row: tap = 2c + part -> 4 x 16B ----
            {
                int tap = 2 * c + part;
                if (tap < 9) {
                    int ky = tap / 3, kx = tap - 3 * ky;
                    const char* sp = smc + P_OFF +
                        (uint32_t)((((ky & 1) * 2 + (kx & 1)) * 4 * 17 + (oy + (ky >> 1))) * 17
                                   + (ox + (kx >> 1))) * 16u;
                    *(uint4*)(dst +  0) = *(const uint4*)(sp);
                    *(uint4*)(dst + 16) = *(const uint4*)(sp + 4624);
                    *(uint4*)(dst + 32) = *(const uint4*)(sp + 2 * 4624);
                    *(uint4*)(dst + 48) = *(const uint4*)(sp + 3 * 4624);
                } else {
                    uint4 z = make_uint4(0, 0, 0, 0);
                    *(uint4*)(dst +  0) = z; *(uint4*)(dst + 16) = z;
                    *(uint4*)(dst + 32) = z; *(uint4*)(dst + 48) = z;
                }
            }
            __syncthreads();

            // ---- 4 k-steps of 16 ----
            #pragma unroll
            for (int ks = 0; ks < 4; ks++) {
                uint32_t af[4];
                ldsm_x4(af, a_lane_base + (uint32_t)ks * 32u);
                uint32_t bf[4][4];
                #pragma unroll
                for (int p = 0; p < 4; p++)
                    ldsm_x4_t(bf[p], b_lane_base + (uint32_t)(c * 64 + ks * 16) * 144u
                                      + (uint32_t)p * 32u);
                #pragma unroll
                for (int j = 0; j < 8; j++)
                    mma16816(acc[j], af, &bf[j >> 1][(j & 1) * 2]);
            }
        }
    }

    // ---- relu + meanpool from fragments ----
    {
        #pragma unroll
        for (int j = 0; j < 8; j++) {
            float s0 = fmaxf(acc[j][0], 0.f) + fmaxf(acc[j][2], 0.f);
            float s1 = fmaxf(acc[j][1], 0.f) + fmaxf(acc[j][3], 0.f);
            s0 += __shfl_xor_sync(0xffffffffu, s0, 4);
            s1 += __shfl_xor_sync(0xffffffffu, s1, 4);
            s0 += __shfl_xor_sync(0xffffffffu, s0, 8);
            s1 += __shfl_xor_sync(0xffffffffu, s1, 8);
            s0 += __shfl_xor_sync(0xffffffffu, s0, 16);
            s1 += __shfl_xor_sync(0xffffffffu, s1, 16);
            if (lane < 4) {
                vec[V_PP + wrp * 64 + j * 8 + lane * 2]     = s0;
                vec[V_PP + wrp * 64 + j * 8 + lane * 2 + 1] = s1;
            }
        }
    }
    __syncthreads();
    if (tid < 64) {
        float s = 0.f;
        #pragma unroll
        for (int w = 0; w < 16; w++) s += vec[V_PP + w * 64 + tid];
        vec[V_POOL + tid] = s * (1.f / 256.f);
    }
    __syncthreads();

    // =====================================================================
    // MLP head (fp32), K-split across lane groups + shfl reduce.
    // All threads run compute with clamped n; only in-range part-0 writes.
    // =====================================================================
    // x1 = relu(pool @ enc_w + enc_b): N=128, K=64, 4-way split
    {
        int nr = tid >> 2, p = tid & 3, n = nr & 127;
        float s = 0.f;
        #pragma unroll
        for (int k = p * 16; k < p * 16 + 16; k++)
            s = fmaf(vec[V_POOL + k], __ldg(&encw[k * 128 + n]), s);
        s += __shfl_xor_sync(0xffffffffu, s, 1);
        s += __shfl_xor_sync(0xffffffffu, s, 2);
        if (p == 0) vec[V_X1 + n] = fmaxf(s + encb[n], 0.f);
    }
    __syncthreads();
    // x2 = relu(x1 @ f1_w + f1_b): N=50, K=128, 4-way
    {
        int nr = tid >> 2, p = tid & 3, n = nr < NVAR ? nr : NVAR - 1;
        float s = 0.f;
        #pragma unroll
        for (int k = p * 32; k < p * 32 + 32; k++)
            s = fmaf(vec[V_X1 + k], __ldg(&f1w[k * NVAR + n]), s);
        s += __shfl_xor_sync(0xffffffffu, s, 1);
        s += __shfl_xor_sync(0xffffffffu, s, 2);
        if (p == 0 && nr < NVAR) vec[V_X2 + n] = fmaxf(s + f1b[n], 0.f);
    }
    __syncthreads();
    // e = C[b] @ x2: N=50, K=50, 4-way (13/13/13/11)
    {
        int nr = tid >> 2, p = tid & 3, n = nr < NVAR ? nr : NVAR - 1;
        const float* cs = (const float*)(smc + CS_OFF);
        int k0 = p * 13, k1 = (p * 13 + 13 < NVAR) ? p * 13 + 13 : NVAR;
        float s = 0.f;
        for (int k = k0; k < k1; k++)
            s = fmaf(cs[n * NVAR + k], vec[V_X2 + k], s);
        s += __shfl_xor_sync(0xffffffffu, s, 1);
        s += __shfl_xor_sync(0xffffffffu, s, 2);
        if (p == 0 && nr < NVAR) vec[V_E + n] = s;
    }
    __syncthreads();
    // x3 = relu(e @ f2_w + f2_b): N=128, K=50, 4-way
    {
        int nr = tid >> 2, p = tid & 3, n = nr & 127;
        int k0 = p * 13, k1 = (p * 13 + 13 < NVAR) ? p * 13 + 13 : NVAR;
        float s = 0.f;
        for (int k = k0; k < k1; k++)
            s = fmaf(vec[V_E + k], __ldg(&f2w[k * 128 + n]), s);
        s += __shfl_xor_sync(0xffffffffu, s, 1);
        s += __shfl_xor_sync(0xffffffffu, s, 2);
        if (p == 0) vec[V_X3 + n] = fmaxf(s + f2b[n], 0.f);
    }
    __syncthreads();
    // x5 = relu(concat(x1,x3) @ f3_w + f3_b): N=64, K=256, 8-way
    {
        int n = (tid >> 3) & 63, p = tid & 7;
        float s = 0.f;
        #pragma unroll
        for (int k = p * 32; k < p * 32 + 32; k++) {
            float v = (k < 128) ? vec[V_X1 + k] : vec[V_X3 + k - 128];
            s = fmaf(v, __ldg(&f3w[k * 64 + n]), s);
        }
        s += __shfl_xor_sync(0xffffffffu, s, 1);
        s += __shfl_xor_sync(0xffffffffu, s, 2);
        s += __shfl_xor_sync(0xffffffffu, s, 4);
        if (p == 0) vec[V_X5 + n] = fmaxf(s + f3b[n], 0.f);
    }
    __syncthreads();
    // x6: N=64, K=64, 4-way (256 threads), others idle-safe via clamp
    {
        int nr = tid >> 2, p = tid & 3, n = nr & 63;
        float s = 0.f;
        #pragma unroll
        for (int k = p * 16; k < p * 16 + 16; k++)
            s = fmaf(vec[V_X5 + k], __ldg(&f4w[k * 64 + n]), s);
        s += __shfl_xor_sync(0xffffffffu, s, 1);
        s += __shfl_xor_sync(0xffffffffu, s, 2);
        if (p == 0 && nr < 64) vec[V_X6 + n] = fmaxf(s + f4b[n], 0.f);
    }
    __syncthreads();
    // x7: N=64, K=64, 4-way
    {
        int nr = tid >> 2, p = tid & 3, n = nr & 63;
        float s = 0.f;
        #pragma unroll
        for (int k = p * 16; k < p * 16 + 16; k++)
            s = fmaf(vec[V_X6 + k], __ldg(&f5w[k * 64 + n]), s);
        s += __shfl_xor_sync(0xffffffffu, s, 1);
        s += __shfl_xor_sync(0xffffffffu, s, 2);
        if (p == 0 && nr < 64) vec[V_X7 + n] = fmaxf(s + f5b[n], 0.f);
    }
    __syncthreads();
    // logits = relu(x7 @ out_w + out_b): N=50, K=64, 4-way
    {
        int nr = tid >> 2, p = tid & 3, n = nr < NVAR ? nr : NVAR - 1;
        float s = 0.f;
        #pragma unroll
        for (int k = p * 16; k < p * 16 + 16; k++)
            s = fmaf(vec[V_X7 + k], __ldg(&ow[k * NVAR + n]), s);
        s += __shfl_xor_sync(0xffffffffu, s, 1);
        s += __shfl_xor_sync(0xffffffffu, s, 2);
        if (p == 0 && nr < NVAR) vec[V_LG + n] = fmaxf(s + ob[n], 0.f);
    }
    __syncthreads();
    // softmax: warp-parallel max/sum in warp 0
    if (tid < 32) {
        float m = vec[V_LG + tid];
        if (tid + 32 < NVAR) m = fmaxf(m, vec[V_LG + tid + 32]);
        #pragma unroll
        for (int off = 16; off > 0; off >>= 1)
            m = fmaxf(m, __shfl_xor_sync(0xffffffffu, m, off));
        if (tid == 0) vec[V_RED] = m;
    }
    __syncthreads();
    if (tid < NVAR) vec[V_LG + tid] = expf(vec[V_LG + tid] - vec[V_RED]);
    __syncthreads();
    if (tid < 32) {
        float s = vec[V_LG + tid];
        if (tid + 32 < NVAR) s += vec[V_LG + tid + 32];
        #pragma unroll
        for (int off = 16; off > 0; off >>= 1)
            s += __shfl_xor_sync(0xffffffffu, s, off);
        if (tid == 0) vec[V_RED + 1] = 1.f / s;
    }
    __syncthreads();
    if (tid < NVAR) out[b * NVAR + tid] = vec[V_LG + tid] * vec[V_RED + 1];
}

extern "C" void kernel_launch(void* const* d_in, const int* in_sizes, int n_in,
                              void* d_out, int out_size)
{
    (void)in_sizes; (void)n_in; (void)out_size;
    const float* x    = (const float*)d_in[0];
    const float* C    = (const float*)d_in[1];
    const float* w1   = (const float*)d_in[2];
    const float* b1   = (const float*)d_in[3];
    const float* w2   = (const float*)d_in[4];
    const float* b2   = (const float*)d_in[5];
    const float* encw = (const float*)d_in[6];
    const float* encb = (const float*)d_in[7];
    const float* f1w  = (const float*)d_in[8];
    const float* f1b  = (const float*)d_in[9];
    const float* f2w  = (const float*)d_in[10];
    const float* f2b  = (const float*)d_in[11];
    const float* f3w  = (const float*)d_in[12];
    const float* f3b  = (const float*)d_in[13];
    const float* f4w  = (const float*)d_in[14];
    const float* f4b  = (const float*)d_in[15];
    const float* f5w  = (const float*)d_in[16];
    const float* f5b  = (const float*)d_in[17];
    const float* ow   = (const float*)d_in[18];
    const float* ob   = (const float*)d_in[19];
    float* out = (float*)d_out;

    b_prep_kernel<<<80, 256>>>(w2);

    cudaFuncSetAttribute(gcp_tc_kernel,
                         cudaFuncAttributeMaxDynamicSharedMemorySize, SMEM_BYTES);

    gcp_tc_kernel<<<4096, NTHREADS, SMEM_BYTES>>>(
        x, C, w1, b1, b2, encw, encb, f1w, f1b, f2w, f2b,
        f3w, f3b, f4w, f4b, f5w, f5b, ow, ob, out);
}

// round 7
// speedup vs baseline: 1.3196x; 1.3196x over previous
#include <cuda_runtime.h>
#include <cuda_bf16.h>
#include <cstdint>

// ===========================================================================
// Fused Goal_Conditioned_Policies forward — both convs on HMMA bf16 with
// DIRECT ldmatrix gather (no im2col materialization).
// One CTA per sample (B=4096), 512 threads, 1 CTA/SM (~209 KB smem).
//   x -> XQ bf16 parity pixels [2][2][33][33][16B] (3 ic + 5 pad)
//   conv1 = GEMM D1[1024 pos][32 oc], K=80 (9 taps x 8-slot, zero-padded),
//           A ldsm'd straight from XQ; writeback -> P parity NHWC bf16
//   conv2 = GEMM D2[256 pos][64 oc], K=288 (9 taps x 32 ic),
//           A ldsm'd straight from P; bias-init acc; relu+meanpool in regs
//   MLP (fp32 K-split) -> softmax
// ===========================================================================

#define NTHREADS 512
#define NVAR     50

// ---- smem byte offsets ----
#define XQ_OFF   0u            // [4 pyx][33][33][16B] = 69,696
#define P_OFF    69696u        // [4 pyx][4 g][17][17][16B] = 73,984
#define B1_OFF   143680u       // conv1 weights [80 k][80 B rows] = 6,400
#define B2_OFF   150080u       // conv2 weights [288 k][144 B rows] = 41,472
#define CS_OFF   191552u       // C[b] 50x50 fp32 = 10,000
#define VEC_OFF  201552u
#define SMEM_BYTES 208896u

#define XQ_REG 17424u          // 33*33*16
#define P_REG  4624u           // 17*17*16

// vec float indices
#define V_B1S  0
#define V_B2S  32
#define V_PP   96        // pool partials [16 warps][64]
#define V_POOL 1120
#define V_X1   1184
#define V_X2   1312
#define V_E    1376
#define V_X3   1440
#define V_X5   1568
#define V_X6   1632
#define V_X7   1696
#define V_LG   1760
#define V_RED  1824

__device__ __forceinline__ uint32_t smem_u32(const void* p) {
    uint32_t a;
    asm("{ .reg .u64 t; cvta.to.shared.u64 t, %1; cvt.u32.u64 %0, t; }" : "=r"(a) : "l"(p));
    return a;
}
__device__ __forceinline__ void ldsm_x4(uint32_t* r, uint32_t addr) {
    asm volatile("ldmatrix.sync.aligned.m8n8.x4.shared.b16 {%0,%1,%2,%3}, [%4];"
        : "=r"(r[0]), "=r"(r[1]), "=r"(r[2]), "=r"(r[3]) : "r"(addr));
}
__device__ __forceinline__ void ldsm_x4_t(uint32_t* r, uint32_t addr) {
    asm volatile("ldmatrix.sync.aligned.m8n8.x4.trans.shared.b16 {%0,%1,%2,%3}, [%4];"
        : "=r"(r[0]), "=r"(r[1]), "=r"(r[2]), "=r"(r[3]) : "r"(addr));
}
__device__ __forceinline__ void mma16816(float* d, const uint32_t* a, const uint32_t* b) {
    asm volatile(
        "mma.sync.aligned.m16n8k16.row.col.f32.bf16.bf16.f32 "
        "{%0,%1,%2,%3}, {%4,%5,%6,%7}, {%8,%9}, {%0,%1,%2,%3};"
        : "+f"(d[0]), "+f"(d[1]), "+f"(d[2]), "+f"(d[3])
        : "r"(a[0]), "r"(a[1]), "r"(a[2]), "r"(a[3]), "r"(b[0]), "r"(b[1]));
}
__device__ __forceinline__ uint32_t pack_bf16x2(float lo, float hi) {
    uint32_t r;
    asm("cvt.rn.bf16x2.f32 %0, %1, %2;" : "=r"(r) : "f"(hi), "f"(lo));
    return r;
}

// --- global weight staging (rebuilt every launch, deterministic) ---
// g_B1: [80 k][40 bf16] (80 B rows). k = tap*8 + j; j<3 -> ic j, else 0.
// g_B2: [288 k][72 bf16] (144 B rows). k = tap*32 + ic.
__device__ __align__(16) __nv_bfloat16 g_B1[80 * 40];
__device__ __align__(16) __nv_bfloat16 g_B2[288 * 72];

__global__ void w_prep_kernel(const float* __restrict__ w1, const float* __restrict__ w2) {
    int i = blockIdx.x * blockDim.x + threadIdx.x;
    if (i < 80 * 40) {
        int kk = i / 40, slot = i - kk * 40;
        int tap = kk >> 3, j = kk & 7;
        float v = 0.f;
        if (slot < 32 && j < 3 && kk < 72)
            v = w1[slot * 27 + j * 9 + tap];    // w1[oc][ic=j][tap]
        g_B1[i] = __float2bfloat16(v);
    }
    int i2 = i - 80 * 40;
    if (i2 >= 0 && i2 < 288 * 72) {
        int kk = i2 / 72, slot = i2 - kk * 72;
        int tap = kk >> 5, ic = kk & 31;
        float v = (slot < 64) ? w2[(slot * 32 + ic) * 9 + tap] : 0.f;
        g_B2[i2] = __float2bfloat16(v);
    }
}

__global__ __launch_bounds__(NTHREADS, 1)
void gcp_tc_kernel(const float* __restrict__ x,    const float* __restrict__ C,
                   const float* __restrict__ b1,   const float* __restrict__ b2,
                   const float* __restrict__ encw, const float* __restrict__ encb,
                   const float* __restrict__ f1w,  const float* __restrict__ f1b,
                   const float* __restrict__ f2w,  const float* __restrict__ f2b,
                   const float* __restrict__ f3w,  const float* __restrict__ f3b,
                   const float* __restrict__ f4w,  const float* __restrict__ f4b,
                   const float* __restrict__ f5w,  const float* __restrict__ f5b,
                   const float* __restrict__ ow,   const float* __restrict__ ob,
                   float* __restrict__ out)
{
    extern __shared__ char smc[];
    const uint32_t smaddr = smem_u32(smc);
    const int b    = blockIdx.x;
    const int tid  = threadIdx.x;
    const int wrp  = tid >> 5;
    const int lane = tid & 31;
    float* vec = (float*)(smc + VEC_OFF);

    // ---- phase A: zero XQ+P, stage B1/B2/C/biases ----
    {
        uint4 z = make_uint4(0, 0, 0, 0);
        for (int i = tid; i < 8980; i += NTHREADS)      // (69696+73984)/16
            ((uint4*)smc)[i] = z;
        const uint4* gb1 = (const uint4*)g_B1;
        for (int i = tid; i < 400; i += NTHREADS)
            ((uint4*)(smc + B1_OFF))[i] = gb1[i];
        const uint4* gb2 = (const uint4*)g_B2;
        for (int i = tid; i < 2592; i += NTHREADS)
            ((uint4*)(smc + B2_OFF))[i] = gb2[i];
        float* cs = (float*)(smc + CS_OFF);
        for (int i = tid; i < 2500; i += NTHREADS) cs[i] = C[b * 2500 + i];
        if (tid < 32) vec[V_B1S + tid] = b1[tid];
        else if (tid < 96) vec[V_B2S + tid - 32] = b2[tid - 32];
    }
    __syncthreads();

    // ---- phase B: x -> XQ bf16 parity pixels ----
    {
        const float4* xg = (const float4*)(x + (size_t)b * 12288);
        for (int i = tid; i < 3072; i += NTHREADS) {
            int ic  = i >> 10;
            int rem = i & 1023;
            int y   = rem >> 4;
            int xc4 = (rem & 15) << 2;
            float4 v = xg[i];
            float vv[4] = {v.x, v.y, v.z, v.w};
            int Y = y + 1;
            uint32_t rbase = XQ_OFF + (uint32_t)((Y & 1) * 2) * XQ_REG
                           + (uint32_t)(Y >> 1) * (33u * 16u) + (uint32_t)ic * 2u;
            #pragma unroll
            for (int j = 0; j < 4; j++) {
                int X = xc4 + j + 1;
                uint32_t off = rbase + (uint32_t)(X & 1) * XQ_REG + (uint32_t)(X >> 1) * 16u;
                *(__nv_bfloat16*)(smc + off) = __float2bfloat16(vv[j]);
            }
        }
    }
    __syncthreads();

    const int r8   = lane & 7;
    const int tsel = lane >> 3;          // tile: mhalf = tsel&1, khalf = tsel>>1
    const int msel = tsel & 1;
    const int khsel = tsel >> 1;

    // =====================================================================
    // conv1 GEMM: D1[1024][32], K=80. Warp w: m-tiles 4w..4w+3.
    // A direct-ldsm from XQ; ks covers taps (2ks, 2ks+1); ks=4 khalf1 = zero.
    // =====================================================================
    float acc1[4][4][4];
    #pragma unroll
    for (int mt = 0; mt < 4; mt++)
        #pragma unroll
        for (int nt = 0; nt < 4; nt++)
            #pragma unroll
            for (int rg = 0; rg < 4; rg++) acc1[mt][nt][rg] = 0.f;
    {
        #pragma unroll
        for (int ks = 0; ks < 5; ks++) {
            // B fragments for this ks (shared by all m-tiles)
            uint32_t bf[2][4];
            {
                uint32_t bb = smaddr + B1_OFF + (uint32_t)(ks * 16 + (lane & 15)) * 80u
                              + (uint32_t)(lane >> 4) * 16u;
                ldsm_x4_t(bf[0], bb);
                ldsm_x4_t(bf[1], bb + 32u);
            }
            const int ta = 2 * ks, tb = 2 * ks + 1;
            const int kya = ta / 3, kxa = ta - 3 * kya;
            const int kyb = (tb < 9) ? tb / 3 : 0, kxb = (tb < 9) ? tb - 3 * kyb : 0;
            #pragma unroll
            for (int mt = 0; mt < 4; mt++) {
                int pos = (wrp * 4 + mt) * 16 + msel * 8 + r8;
                int oy1 = pos >> 5, ox1 = pos & 31;
                uint32_t addr_e = XQ_OFF + (uint32_t)((kya & 1) * 2 + (kxa & 1)) * XQ_REG
                    + (uint32_t)((oy1 + (kya >> 1)) * 33 + ox1 + (kxa >> 1)) * 16u;
                uint32_t addr_o = (tb < 9)
                    ? XQ_OFF + (uint32_t)((kyb & 1) * 2 + (kxb & 1)) * XQ_REG
                      + (uint32_t)((oy1 + (kyb >> 1)) * 33 + ox1 + (kxb >> 1)) * 16u
                    : XQ_OFF;                       // zeroed slot (Y=0,X=0 never written)
                uint32_t af[4];
                ldsm_x4(af, smaddr + (khsel ? addr_o : addr_e));
                #pragma unroll
                for (int nt = 0; nt < 4; nt++)
                    mma16816(acc1[mt][nt], af, &bf[nt >> 1][(nt & 1) * 2]);
            }
        }
    }

    // ---- writeback: relu(acc1 + b1) -> P (packed bf16x2 u32 stores) ----
    {
        #pragma unroll
        for (int nt = 0; nt < 4; nt++) {
            int n = nt * 8 + (lane & 3) * 2;
            float bb0 = vec[V_B1S + n], bb1 = vec[V_B1S + n + 1];
            uint32_t greg = (uint32_t)(n >> 3) * P_REG;
            uint32_t sub  = (uint32_t)(n & 7) * 2u;
            #pragma unroll
            for (int mt = 0; mt < 4; mt++) {
                #pragma unroll
                for (int hh = 0; hh < 2; hh++) {
                    int pos = (wrp * 4 + mt) * 16 + (lane >> 2) + hh * 8;
                    int Y = (pos >> 5) + 1, X = (pos & 31) + 1;
                    float v0 = fmaxf(acc1[mt][nt][hh * 2 + 0] + bb0, 0.f);
                    float v1 = fmaxf(acc1[mt][nt][hh * 2 + 1] + bb1, 0.f);
                    uint32_t off = P_OFF + (uint32_t)((Y & 1) * 2 + (X & 1)) * (4u * P_REG)
                        + greg + (uint32_t)((Y >> 1) * 17 + (X >> 1)) * 16u + sub;
                    *(uint32_t*)(smc + off) = pack_bf16x2(v0, v1);
                }
            }
        }
    }
    __syncthreads();

    // =====================================================================
    // conv2 GEMM: D2[256][64], K=288. Warp w: m-tile w. A direct-ldsm from P.
    // =====================================================================
    float acc2[8][4];
    {
        const int cB = (lane & 3) * 2;
        #pragma unroll
        for (int j = 0; j < 8; j++) {
            float b0  = vec[V_B2S + j * 8 + cB];
            float b1v = vec[V_B2S + j * 8 + cB + 1];
            acc2[j][0] = b0;  acc2[j][1] = b1v;
            acc2[j][2] = b0;  acc2[j][3] = b1v;
        }
    }
    {
        const int pos = wrp * 16 + msel * 8 + r8;
        const int oy2 = pos >> 4, ox2 = pos & 15;
        #pragma unroll
        for (int tap = 0; tap < 9; tap++) {
            const int ky = tap / 3, kx = tap - 3 * ky;
            uint32_t rbase = P_OFF + (uint32_t)((ky & 1) * 2 + (kx & 1)) * (4u * P_REG)
                + (uint32_t)khsel * P_REG
                + (uint32_t)((oy2 + (ky >> 1)) * 17 + (ox2 + (kx >> 1))) * 16u;
            #pragma unroll
            for (int gh = 0; gh < 2; gh++) {
                uint32_t af[4];
                ldsm_x4(af, smaddr + rbase + (uint32_t)gh * (2u * P_REG));
                uint32_t bf[4][4];
                uint32_t bb = smaddr + B2_OFF
                    + (uint32_t)((tap * 32 + gh * 16) + (lane & 15)) * 144u
                    + (uint32_t)(lane >> 4) * 16u;
                #pragma unroll
                for (int p = 0; p < 4; p++) ldsm_x4_t(bf[p], bb + (uint32_t)p * 32u);
                #pragma unroll
                for (int j = 0; j < 8; j++)
                    mma16816(acc2[j], af, &bf[j >> 1][(j & 1) * 2]);
            }
        }
    }

    // ---- relu + meanpool from fragments ----
    {
        #pragma unroll
        for (int j = 0; j < 8; j++) {
            float s0 = fmaxf(acc2[j][0], 0.f) + fmaxf(acc2[j][2], 0.f);
            float s1 = fmaxf(acc2[j][1], 0.f) + fmaxf(acc2[j][3], 0.f);
            s0 += __shfl_xor_sync(0xffffffffu, s0, 4);
            s1 += __shfl_xor_sync(0xffffffffu, s1, 4);
            s0 += __shfl_xor_sync(0xffffffffu, s0, 8);
            s1 += __shfl_xor_sync(0xffffffffu, s1, 8);
            s0 += __shfl_xor_sync(0xffffffffu, s0, 16);
            s1 += __shfl_xor_sync(0xffffffffu, s1, 16);
            if (lane < 4) {
                vec[V_PP + wrp * 64 + j * 8 + lane * 2]     = s0;
                vec[V_PP + wrp * 64 + j * 8 + lane * 2 + 1] = s1;
            }
        }
    }
    __syncthreads();
    if (tid < 64) {
        float s = 0.f;
        #pragma unroll
        for (int w = 0; w < 16; w++) s += vec[V_PP + w * 64 + tid];
        vec[V_POOL + tid] = s * (1.f / 256.f);
    }
    __syncthreads();

    // =====================================================================
    // MLP head (fp32), K-split across lane groups + shfl reduce.
    // =====================================================================
    {
        int nr = tid >> 2, p = tid & 3, n = nr & 127;
        float s = 0.f;
        #pragma unroll
        for (int k = p * 16; k < p * 16 + 16; k++)
            s = fmaf(vec[V_POOL + k], __ldg(&encw[k * 128 + n]), s);
        s += __shfl_xor_sync(0xffffffffu, s, 1);
        s += __shfl_xor_sync(0xffffffffu, s, 2);
        if (p == 0) vec[V_X1 + n] = fmaxf(s + encb[n], 0.f);
    }
    __syncthreads();
    {
        int nr = tid >> 2, p = tid & 3, n = nr < NVAR ? nr : NVAR - 1;
        float s = 0.f;
        #pragma unroll
        for (int k = p * 32; k < p * 32 + 32; k++)
            s = fmaf(vec[V_X1 + k], __ldg(&f1w[k * NVAR + n]), s);
        s += __shfl_xor_sync(0xffffffffu, s, 1);
        s += __shfl_xor_sync(0xffffffffu, s, 2);
        if (p == 0 && nr < NVAR) vec[V_X2 + n] = fmaxf(s + f1b[n], 0.f);
    }
    __syncthreads();
    {
        int nr = tid >> 2, p = tid & 3, n = nr < NVAR ? nr : NVAR - 1;
        const float* cs = (const float*)(smc + CS_OFF);
        int k0 = p * 13, k1 = (p * 13 + 13 < NVAR) ? p * 13 + 13 : NVAR;
        float s = 0.f;
        for (int k = k0; k < k1; k++)
            s = fmaf(cs[n * NVAR + k], vec[V_X2 + k], s);
        s += __shfl_xor_sync(0xffffffffu, s, 1);
        s += __shfl_xor_sync(0xffffffffu, s, 2);
        if (p == 0 && nr < NVAR) vec[V_E + n] = s;
    }
    __syncthreads();
    {
        int nr = tid >> 2, p = tid & 3, n = nr & 127;
        int k0 = p * 13, k1 = (p * 13 + 13 < NVAR) ? p * 13 + 13 : NVAR;
        float s = 0.f;
        for (int k = k0; k < k1; k++)
            s = fmaf(vec[V_E + k], __ldg(&f2w[k * 128 + n]), s);
        s += __shfl_xor_sync(0xffffffffu, s, 1);
        s += __shfl_xor_sync(0xffffffffu, s, 2);
        if (p == 0) vec[V_X3 + n] = fmaxf(s + f2b[n], 0.f);
    }
    __syncthreads();
    {
        int n = (tid >> 3) & 63, p = tid & 7;
        float s = 0.f;
        #pragma unroll
        for (int k = p * 32; k < p * 32 + 32; k++) {
            float v = (k < 128) ? vec[V_X1 + k] : vec[V_X3 + k - 128];
            s = fmaf(v, __ldg(&f3w[k * 64 + n]), s);
        }
        s += __shfl_xor_sync(0xffffffffu, s, 1);
        s += __shfl_xor_sync(0xffffffffu, s, 2);
        s += __shfl_xor_sync(0xffffffffu, s, 4);
        if (p == 0) vec[V_X5 + n] = fmaxf(s + f3b[n], 0.f);
    }
    __syncthreads();
    {
        int nr = tid >> 2, p = tid & 3, n = nr & 63;
        float s = 0.f;
        #pragma unroll
        for (int k = p * 16; k < p * 16 + 16; k++)
            s = fmaf(vec[V_X5 + k], __ldg(&f4w[k * 64 + n]), s);
        s += __shfl_xor_sync(0xffffffffu, s, 1);
        s += __shfl_xor_sync(0xffffffffu, s, 2);
        if (p == 0 && nr < 64) vec[V_X6 + n] = fmaxf(s + f4b[n], 0.f);
    }
    __syncthreads();
    {
        int nr = tid >> 2, p = tid & 3, n = nr & 63;
        float s = 0.f;
        #pragma unroll
        for (int k = p * 16; k < p * 16 + 16; k++)
            s = fmaf(vec[V_X6 + k], __ldg(&f5w[k * 64 + n]), s);
        s += __shfl_xor_sync(0xffffffffu, s, 1);
        s += __shfl_xor_sync(0xffffffffu, s, 2);
        if (p == 0 && nr < 64) vec[V_X7 + n] = fmaxf(s + f5b[n], 0.f);
    }
    __syncthreads();
    {
        int nr = tid >> 2, p = tid & 3, n = nr < NVAR ? nr : NVAR - 1;
        float s = 0.f;
        #pragma unroll
        for (int k = p * 16; k < p * 16 + 16; k++)
            s = fmaf(vec[V_X7 + k], __ldg(&ow[k * NVAR + n]), s);
        s += __shfl_xor_sync(0xffffffffu, s, 1);
        s += __shfl_xor_sync(0xffffffffu, s, 2);
        if (p == 0 && nr < NVAR) vec[V_LG + n] = fmaxf(s + ob[n], 0.f);
    }
    __syncthreads();
    if (tid < 32) {
        float m = vec[V_LG + tid];
        if (tid + 32 < NVAR) m = fmaxf(m, vec[V_LG + tid + 32]);
        #pragma unroll
        for (int off = 16; off > 0; off >>= 1)
            m = fmaxf(m, __shfl_xor_sync(0xffffffffu, m, off));
        if (tid == 0) vec[V_RED] = m;
    }
    __syncthreads();
    if (tid < NVAR) vec[V_LG + tid] = expf(vec[V_LG + tid] - vec[V_RED]);
    __syncthreads();
    if (tid < 32) {
        float s = vec[V_LG + tid];
        if (tid + 32 < NVAR) s += vec[V_LG + tid + 32];
        #pragma unroll
        for (int off = 16; off > 0; off >>= 1)
            s += __shfl_xor_sync(0xffffffffu, s, off);
        if (tid == 0) vec[V_RED + 1] = 1.f / s;
    }
    __syncthreads();
    if (tid < NVAR) out[b * NVAR + tid] = vec[V_LG + tid] * vec[V_RED + 1];
}

extern "C" void kernel_launch(void* const* d_in, const int* in_sizes, int n_in,
                              void* d_out, int out_size)
{
    (void)in_sizes; (void)n_in; (void)out_size;
    const float* x    = (const float*)d_in[0];
    const float* C    = (const float*)d_in[1];
    const float* w1   = (const float*)d_in[2];
    const float* b1   = (const float*)d_in[3];
    const float* w2   = (const float*)d_in[4];
    const float* b2   = (const float*)d_in[5];
    const float* encw = (const float*)d_in[6];
    const float* encb = (const float*)d_in[7];
    const float* f1w  = (const float*)d_in[8];
    const float* f1b  = (const float*)d_in[9];
    const float* f2w  = (const float*)d_in[10];
    const float* f2b  = (const float*)d_in[11];
    const float* f3w  = (const float*)d_in[12];
    const float* f3b  = (const float*)d_in[13];
    const float* f4w  = (const float*)d_in[14];
    const float* f4b  = (const float*)d_in[15];
    const float* f5w  = (const float*)d_in[16];
    const float* f5b  = (const float*)d_in[17];
    const float* ow   = (const float*)d_in[18];
    const float* ob   = (const float*)d_in[19];
    float* out = (float*)d_out;

    w_prep_kernel<<<94, 256>>>(w1, w2);

    cudaFuncSetAttribute(gcp_tc_kernel,
                         cudaFuncAttributeMaxDynamicSharedMemorySize, SMEM_BYTES);

    gcp_tc_kernel<<<4096, NTHREADS, SMEM_BYTES>>>(
        x, C, b1, b2, encw, encb, f1w, f1b, f2w, f2b,
        f3w, f3b, f4w, f4b, f5w, f5b, ow, ob, out);
}

// round 8
// speedup vs baseline: 1.6487x; 1.2494x over previous
#include <cuda_runtime.h>
#include <cuda_bf16.h>
#include <cstdint>

// ===========================================================================
// Goal_Conditioned_Policies forward, two-kernel design.
// K1 (per-sample CTA, 512 thr): conv1+conv2 on HMMA bf16 w/ direct ldmatrix
//    gather, relu+meanpool -> g_pool[4096][64].
// K2 (warp-per-sample, no smem, no barriers): MLP + C matvec + softmax, all
//    activations in registers via shfl; weights L2-resident.
// ===========================================================================

#define NTHREADS 512
#define NVAR     50

// ---- K1 smem byte offsets ----
#define XQ_OFF   0u            // [4 pyx][33][33][16B] = 69,696
#define P_OFF    69696u        // [4 pyx][4 g][17][17][16B] = 73,984
#define B1_OFF   143680u       // conv1 weights [80 k][80 B rows] = 6,400
#define B2_OFF   150080u       // conv2 weights [288 k][144 B rows] = 41,472
#define VEC_OFF  191552u
#define SMEM_BYTES 194048u

#define XQ_REG 17424u          // 33*33*16
#define P_REG  4624u           // 17*17*16

// vec float indices
#define V_B1S  0
#define V_B2S  32
#define V_PP   96        // pool partials [16 warps][32]

__device__ __forceinline__ uint32_t smem_u32(const void* p) {
    uint32_t a;
    asm("{ .reg .u64 t; cvta.to.shared.u64 t, %1; cvt.u32.u64 %0, t; }" : "=r"(a) : "l"(p));
    return a;
}
__device__ __forceinline__ void ldsm_x4(uint32_t* r, uint32_t addr) {
    asm volatile("ldmatrix.sync.aligned.m8n8.x4.shared.b16 {%0,%1,%2,%3}, [%4];"
        : "=r"(r[0]), "=r"(r[1]), "=r"(r[2]), "=r"(r[3]) : "r"(addr));
}
__device__ __forceinline__ void ldsm_x4_t(uint32_t* r, uint32_t addr) {
    asm volatile("ldmatrix.sync.aligned.m8n8.x4.trans.shared.b16 {%0,%1,%2,%3}, [%4];"
        : "=r"(r[0]), "=r"(r[1]), "=r"(r[2]), "=r"(r[3]) : "r"(addr));
}
__device__ __forceinline__ void mma16816(float* d, const uint32_t* a, const uint32_t* b) {
    asm volatile(
        "mma.sync.aligned.m16n8k16.row.col.f32.bf16.bf16.f32 "
        "{%0,%1,%2,%3}, {%4,%5,%6,%7}, {%8,%9}, {%0,%1,%2,%3};"
        : "+f"(d[0]), "+f"(d[1]), "+f"(d[2]), "+f"(d[3])
        : "r"(a[0]), "r"(a[1]), "r"(a[2]), "r"(a[3]), "r"(b[0]), "r"(b[1]));
}
__device__ __forceinline__ uint32_t pack_bf16x2(float lo, float hi) {
    uint32_t r;
    asm("cvt.rn.bf16x2.f32 %0, %1, %2;" : "=r"(r) : "f"(hi), "f"(lo));
    return r;
}

// --- global scratch (static device arrays; rebuilt deterministically) ---
__device__ __align__(16) __nv_bfloat16 g_B1[80 * 40];
__device__ __align__(16) __nv_bfloat16 g_B2[288 * 72];
__device__ __align__(16) float g_pool[4096 * 64];

__global__ void w_prep_kernel(const float* __restrict__ w1, const float* __restrict__ w2) {
    int i = blockIdx.x * blockDim.x + threadIdx.x;
    if (i < 80 * 40) {
        int kk = i / 40, slot = i - kk * 40;
        int tap = kk >> 3, j = kk & 7;
        float v = 0.f;
        if (slot < 32 && j < 3 && kk < 72)
            v = w1[slot * 27 + j * 9 + tap];    // w1[oc][ic=j][tap]
        g_B1[i] = __float2bfloat16(v);
    }
    int i2 = i - 80 * 40;
    if (i2 >= 0 && i2 < 288 * 72) {
        int kk = i2 / 72, slot = i2 - kk * 72;
        int tap = kk >> 5, ic = kk & 31;
        float v = (slot < 64) ? w2[(slot * 32 + ic) * 9 + tap] : 0.f;
        g_B2[i2] = __float2bfloat16(v);
    }
}

// ===========================================================================
// K1: convs + pool
// ===========================================================================
__global__ __launch_bounds__(NTHREADS, 1)
void gcp_conv_kernel(const float* __restrict__ x,
                     const float* __restrict__ b1, const float* __restrict__ b2)
{
    extern __shared__ char smc[];
    const uint32_t smaddr = smem_u32(smc);
    const int b    = blockIdx.x;
    const int tid  = threadIdx.x;
    const int wrp  = tid >> 5;
    const int lane = tid & 31;
    float* vec = (float*)(smc + VEC_OFF);

    // ---- stage: zero XQ+P, B1/B2/biases ----
    {
        uint4 z = make_uint4(0, 0, 0, 0);
        for (int i = tid; i < 8980; i += NTHREADS)      // (69696+73984)/16
            ((uint4*)smc)[i] = z;
        const uint4* gb1 = (const uint4*)g_B1;
        for (int i = tid; i < 400; i += NTHREADS)
            ((uint4*)(smc + B1_OFF))[i] = gb1[i];
        const uint4* gb2 = (const uint4*)g_B2;
        for (int i = tid; i < 2592; i += NTHREADS)
            ((uint4*)(smc + B2_OFF))[i] = gb2[i];
        if (tid < 32) vec[V_B1S + tid] = b1[tid];
        else if (tid < 96) vec[V_B2S + tid - 32] = b2[tid - 32];
    }
    __syncthreads();

    // ---- x -> XQ bf16 parity pixels ----
    {
        const float4* xg = (const float4*)(x + (size_t)b * 12288);
        for (int i = tid; i < 3072; i += NTHREADS) {
            int ic  = i >> 10;
            int rem = i & 1023;
            int y   = rem >> 4;
            int xc4 = (rem & 15) << 2;
            float4 v = xg[i];
            float vv[4] = {v.x, v.y, v.z, v.w};
            int Y = y + 1;
            uint32_t rbase = XQ_OFF + (uint32_t)((Y & 1) * 2) * XQ_REG
                           + (uint32_t)(Y >> 1) * (33u * 16u) + (uint32_t)ic * 2u;
            #pragma unroll
            for (int j = 0; j < 4; j++) {
                int X = xc4 + j + 1;
                uint32_t off = rbase + (uint32_t)(X & 1) * XQ_REG + (uint32_t)(X >> 1) * 16u;
                *(__nv_bfloat16*)(smc + off) = __float2bfloat16(vv[j]);
            }
        }
    }
    __syncthreads();

    const int r8    = lane & 7;
    const int msel  = (lane >> 3) & 1;
    const int khsel = lane >> 4;

    // =====================================================================
    // conv1 GEMM: D1[1024][32], K=80. Warp w: m-tiles 4w..4w+3.
    // =====================================================================
    float acc1[4][4][4];
    #pragma unroll
    for (int mt = 0; mt < 4; mt++)
        #pragma unroll
        for (int nt = 0; nt < 4; nt++)
            #pragma unroll
            for (int rg = 0; rg < 4; rg++) acc1[mt][nt][rg] = 0.f;
    {
        #pragma unroll
        for (int ks = 0; ks < 5; ks++) {
            uint32_t bf[2][4];
            {
                uint32_t bb = smaddr + B1_OFF + (uint32_t)(ks * 16 + (lane & 15)) * 80u
                              + (uint32_t)(lane >> 4) * 16u;
                ldsm_x4_t(bf[0], bb);
                ldsm_x4_t(bf[1], bb + 32u);
            }
            const int ta = 2 * ks, tb = 2 * ks + 1;
            const int kya = ta / 3, kxa = ta - 3 * kya;
            const int kyb = (tb < 9) ? tb / 3 : 0, kxb = (tb < 9) ? tb - 3 * kyb : 0;
            #pragma unroll
            for (int mt = 0; mt < 4; mt++) {
                int pos = (wrp * 4 + mt) * 16 + msel * 8 + r8;
                int oy1 = pos >> 5, ox1 = pos & 31;
                uint32_t addr_e = XQ_OFF + (uint32_t)((kya & 1) * 2 + (kxa & 1)) * XQ_REG
                    + (uint32_t)((oy1 + (kya >> 1)) * 33 + ox1 + (kxa >> 1)) * 16u;
                uint32_t addr_o = (tb < 9)
                    ? XQ_OFF + (uint32_t)((kyb & 1) * 2 + (kxb & 1)) * XQ_REG
                      + (uint32_t)((oy1 + (kyb >> 1)) * 33 + ox1 + (kxb >> 1)) * 16u
                    : XQ_OFF;                       // zeroed halo slot
                uint32_t af[4];
                ldsm_x4(af, smaddr + (khsel ? addr_o : addr_e));
                #pragma unroll
                for (int nt = 0; nt < 4; nt++)
                    mma16816(acc1[mt][nt], af, &bf[nt >> 1][(nt & 1) * 2]);
            }
        }
    }

    // ---- writeback: relu(acc1 + b1) -> P ----
    {
        #pragma unroll
        for (int nt = 0; nt < 4; nt++) {
            int n = nt * 8 + (lane & 3) * 2;
            float bb0 = vec[V_B1S + n], bb1 = vec[V_B1S + n + 1];
            uint32_t greg = (uint32_t)(n >> 3) * P_REG;
            uint32_t sub  = (uint32_t)(n & 7) * 2u;
            #pragma unroll
            for (int mt = 0; mt < 4; mt++) {
                #pragma unroll
                for (int hh = 0; hh < 2; hh++) {
                    int pos = (wrp * 4 + mt) * 16 + (lane >> 2) + hh * 8;
                    int Y = (pos >> 5) + 1, X = (pos & 31) + 1;
                    float v0 = fmaxf(acc1[mt][nt][hh * 2 + 0] + bb0, 0.f);
                    float v1 = fmaxf(acc1[mt][nt][hh * 2 + 1] + bb1, 0.f);
                    uint32_t off = P_OFF + (uint32_t)((Y & 1) * 2 + (X & 1)) * (4u * P_REG)
                        + greg + (uint32_t)((Y >> 1) * 17 + (X >> 1)) * 16u + sub;
                    *(uint32_t*)(smc + off) = pack_bf16x2(v0, v1);
                }
            }
        }
    }
    __syncthreads();

    // =====================================================================
    // conv2 GEMM: D2[256][64]. Warp w: m-tiles {2(w&7), 2(w&7)+1},
    // n-tiles [4(w>>3), 4(w>>3)+4). A direct-ldsm from P.
    // =====================================================================
    const int mt0 = (wrp & 7) * 2;
    const int nh  = wrp >> 3;
    float acc2[2][4][4];
    {
        #pragma unroll
        for (int jl = 0; jl < 4; jl++) {
            int oc = nh * 32 + jl * 8 + (lane & 3) * 2;
            float b0  = vec[V_B2S + oc];
            float b1v = vec[V_B2S + oc + 1];
            #pragma unroll
            for (int mt = 0; mt < 2; mt++) {
                acc2[mt][jl][0] = b0;  acc2[mt][jl][1] = b1v;
                acc2[mt][jl][2] = b0;  acc2[mt][jl][3] = b1v;
            }
        }
    }
    {
        const int ox2 = msel * 8 + r8;
        #pragma unroll
        for (int tap = 0; tap < 9; tap++) {
            const int ky = tap / 3, kx = tap - 3 * ky;
            const uint32_t pbase = P_OFF + (uint32_t)((ky & 1) * 2 + (kx & 1)) * (4u * P_REG)
                + (uint32_t)khsel * P_REG + (uint32_t)(ox2 + (kx >> 1)) * 16u;
            #pragma unroll
            for (int gh = 0; gh < 2; gh++) {
                uint32_t af[2][4];
                #pragma unroll
                for (int mt = 0; mt < 2; mt++) {
                    uint32_t ra = pbase + (uint32_t)gh * (2u * P_REG)
                        + (uint32_t)((mt0 + mt + (ky >> 1)) * 17) * 16u;
                    ldsm_x4(af[mt], smaddr + ra);
                }
                uint32_t bf[2][4];
                uint32_t bb = smaddr + B2_OFF
                    + (uint32_t)((tap * 32 + gh * 16) + (lane & 15)) * 144u
                    + (uint32_t)(lane >> 4) * 16u + (uint32_t)(2 * nh) * 32u;
                ldsm_x4_t(bf[0], bb);
                ldsm_x4_t(bf[1], bb + 32u);
                #pragma unroll
                for (int mt = 0; mt < 2; mt++)
                    #pragma unroll
                    for (int jl = 0; jl < 4; jl++)
                        mma16816(acc2[mt][jl], af[mt], &bf[jl >> 1][(jl & 1) * 2]);
            }
        }
    }

    // ---- relu + meanpool from fragments ----
    {
        #pragma unroll
        for (int jl = 0; jl < 4; jl++) {
            float s0 = 0.f, s1 = 0.f;
            #pragma unroll
            for (int mt = 0; mt < 2; mt++) {
                s0 += fmaxf(acc2[mt][jl][0], 0.f) + fmaxf(acc2[mt][jl][2], 0.f);
                s1 += fmaxf(acc2[mt][jl][1], 0.f) + fmaxf(acc2[mt][jl][3], 0.f);
            }
            s0 += __shfl_xor_sync(0xffffffffu, s0, 4);
            s1 += __shfl_xor_sync(0xffffffffu, s1, 4);
            s0 += __shfl_xor_sync(0xffffffffu, s0, 8);
            s1 += __shfl_xor_sync(0xffffffffu, s1, 8);
            s0 += __shfl_xor_sync(0xffffffffu, s0, 16);
            s1 += __shfl_xor_sync(0xffffffffu, s1, 16);
            if (lane < 4) {
                vec[V_PP + wrp * 32 + jl * 8 + lane * 2]     = s0;
                vec[V_PP + wrp * 32 + jl * 8 + lane * 2 + 1] = s1;
            }
        }
    }
    __syncthreads();
    if (tid < 64) {
        int nhh = tid >> 5, oc32 = tid & 31;
        float s = 0.f;
        #pragma unroll
        for (int mp = 0; mp < 8; mp++)
            s += vec[V_PP + (nhh * 8 + mp) * 32 + oc32];
        g_pool[b * 64 + tid] = s * (1.f / 256.f);
    }
}

// ===========================================================================
// K2: warp-per-sample MLP + C matvec + softmax. No smem, no barriers.
// Lane n-mapping per layer; activations broadcast via shfl.
// ===========================================================================
__global__ __launch_bounds__(256, 4)
void gcp_mlp_kernel(const float* __restrict__ C,
                    const float* __restrict__ encw, const float* __restrict__ encb,
                    const float* __restrict__ f1w,  const float* __restrict__ f1b,
                    const float* __restrict__ f2w,  const float* __restrict__ f2b,
                    const float* __restrict__ f3w,  const float* __restrict__ f3b,
                    const float* __restrict__ f4w,  const float* __restrict__ f4b,
                    const float* __restrict__ f5w,  const float* __restrict__ f5b,
                    const float* __restrict__ ow,   const float* __restrict__ ob,
                    float* __restrict__ out)
{
    const int s    = blockIdx.x * 8 + (threadIdx.x >> 5);
    const int lane = threadIdx.x & 31;
    const unsigned FULL = 0xffffffffu;

    const float p0 = g_pool[s * 64 + lane];
    const float p1 = g_pool[s * 64 + 32 + lane];

    // x1[128] = relu(pool @ encw + encb); lane holds n = lane + 32j
    float x1r[4];
    #pragma unroll
    for (int j = 0; j < 4; j++) x1r[j] = encb[lane + 32 * j];
    #pragma unroll 4
    for (int k = 0; k < 64; k++) {
        float v = (k < 32) ? __shfl_sync(FULL, p0, k) : __shfl_sync(FULL, p1, k - 32);
        #pragma unroll
        for (int j = 0; j < 4; j++)
            x1r[j] = fmaf(v, __ldg(&encw[k * 128 + lane + 32 * j]), x1r[j]);
    }
    #pragma unroll
    for (int j = 0; j < 4; j++) x1r[j] = fmaxf(x1r[j], 0.f);

    // x2[50]: lane holds n = lane (a0) and n = lane+32 for lane<18 (a1)
    float a0 = f1b[lane];
    float a1 = (lane < 18) ? f1b[lane + 32] : 0.f;
    const int nc = (lane < 18) ? lane + 32 : 49;   // clamped 2nd index
    #pragma unroll 4
    for (int k = 0; k < 128; k++) {
        float v = __shfl_sync(FULL, x1r[k >> 5], k & 31);
        a0 = fmaf(v, __ldg(&f1w[k * NVAR + lane]), a0);
        a1 = fmaf(v, __ldg(&f1w[k * NVAR + nc]), a1);
    }
    float x2a = fmaxf(a0, 0.f);
    float x2b = fmaxf(a1, 0.f);

    // e[50] = C[s] @ x2; lane-parallel over k, butterfly-reduce per row
    float ea = 0.f, eb = 0.f;
    {
        const float* cs = C + (size_t)s * 2500;
        for (int n = 0; n < NVAR; n++) {
            float t = __ldg(&cs[n * NVAR + lane]) * x2a;
            if (lane < 18) t = fmaf(__ldg(&cs[n * NVAR + 32 + lane]), x2b, t);
            #pragma unroll
            for (int off = 16; off > 0; off >>= 1)
                t += __shfl_xor_sync(FULL, t, off);
            if (n < 32) { if (lane == n) ea = t; }
            else        { if (lane == n - 32) eb = t; }
        }
    }

    // x3[128] = relu(e @ f2w + f2b)
    float x3r[4];
    #pragma unroll
    for (int j = 0; j < 4; j++) x3r[j] = f2b[lane + 32 * j];
    #pragma unroll 2
    for (int k = 0; k < NVAR; k++) {
        float v = (k < 32) ? __shfl_sync(FULL, ea, k) : __shfl_sync(FULL, eb, k - 32);
        #pragma unroll
        for (int j = 0; j < 4; j++)
            x3r[j] = fmaf(v, __ldg(&f2w[k * 128 + lane + 32 * j]), x3r[j]);
    }
    #pragma unroll
    for (int j = 0; j < 4; j++) x3r[j] = fmaxf(x3r[j], 0.f);

    // x5[64] = relu(concat(x1,x3) @ f3w + f3b)
    float b0 = f3b[lane], b1v = f3b[lane + 32];
    #pragma unroll 4
    for (int k = 0; k < 256; k++) {
        float v = (k < 128) ? __shfl_sync(FULL, x1r[k >> 5], k & 31)
                            : __shfl_sync(FULL, x3r[(k - 128) >> 5], (k - 128) & 31);
        b0  = fmaf(v, __ldg(&f3w[k * 64 + lane]), b0);
        b1v = fmaf(v, __ldg(&f3w[k * 64 + lane + 32]), b1v);
    }
    float x5a = fmaxf(b0, 0.f), x5b = fmaxf(b1v, 0.f);

    // x6[64]
    float c0 = f4b[lane], c1 = f4b[lane + 32];
    #pragma unroll 4
    for (int k = 0; k < 64; k++) {
        float v = (k < 32) ? __shfl_sync(FULL, x5a, k) : __shfl_sync(FULL, x5b, k - 32);
        c0 = fmaf(v, __ldg(&f4w[k * 64 + lane]), c0);
        c1 = fmaf(v, __ldg(&f4w[k * 64 + lane + 32]), c1);
    }
    float x6a = fmaxf(c0, 0.f), x6b = fmaxf(c1, 0.f);

    // x7[64]
    float d0 = f5b[lane], d1 = f5b[lane + 32];
    #pragma unroll 4
    for (int k = 0; k < 64; k++) {
        float v = (k < 32) ? __shfl_sync(FULL, x6a, k) : __shfl_sync(FULL, x6b, k - 32);
        d0 = fmaf(v, __ldg(&f5w[k * 64 + lane]), d0);
        d1 = fmaf(v, __ldg(&f5w[k * 64 + lane + 32]), d1);
    }
    float x7a = fmaxf(d0, 0.f), x7b = fmaxf(d1, 0.f);

    // logits[50] = relu(x7 @ ow + ob)
    float l0 = ob[lane];
    float l1 = (lane < 18) ? ob[lane + 32] : 0.f;
    #pragma unroll 4
    for (int k = 0; k < 64; k++) {
        float v = (k < 32) ? __shfl_sync(FULL, x7a, k) : __shfl_sync(FULL, x7b, k - 32);
        l0 = fmaf(v, __ldg(&ow[k * NVAR + lane]), l0);
        l1 = fmaf(v, __ldg(&ow[k * NVAR + nc]), l1);
    }
    l0 = fmaxf(l0, 0.f);
    l1 = (lane < 18) ? fmaxf(l1, 0.f) : -1e30f;

    // softmax over 50
    float m = fmaxf(l0, l1);
    #pragma unroll
    for (int off = 16; off > 0; off >>= 1)
        m = fmaxf(m, __shfl_xor_sync(FULL, m, off));
    float e0 = expf(l0 - m);
    float e1 = (lane < 18) ? expf(l1 - m) : 0.f;
    float ssum = e0 + e1;
    #pragma unroll
    for (int off = 16; off > 0; off >>= 1)
        ssum += __shfl_xor_sync(FULL, ssum, off);
    float inv = 1.f / ssum;
    out[s * NVAR + lane] = e0 * inv;
    if (lane < 18) out[s * NVAR + 32 + lane] = e1 * inv;
}

extern "C" void kernel_launch(void* const* d_in, const int* in_sizes, int n_in,
                              void* d_out, int out_size)
{
    (void)in_sizes; (void)n_in; (void)out_size;
    const float* x    = (const float*)d_in[0];
    const float* C    = (const float*)d_in[1];
    const float* w1   = (const float*)d_in[2];
    const float* b1   = (const float*)d_in[3];
    const float* w2   = (const float*)d_in[4];
    const float* b2   = (const float*)d_in[5];
    const float* encw = (const float*)d_in[6];
    const float* encb = (const float*)d_in[7];
    const float* f1w  = (const float*)d_in[8];
    const float* f1b  = (const float*)d_in[9];
    const float* f2w  = (const float*)d_in[10];
    const float* f2b  = (const float*)d_in[11];
    const float* f3w  = (const float*)d_in[12];
    const float* f3b  = (const float*)d_in[13];
    const float* f4w  = (const float*)d_in[14];
    const float* f4b  = (const float*)d_in[15];
    const float* f5w  = (const float*)d_in[16];
    const float* f5b  = (const float*)d_in[17];
    const float* ow   = (const float*)d_in[18];
    const float* ob   = (const float*)d_in[19];
    float* out = (float*)d_out;

    w_prep_kernel<<<94, 256>>>(w1, w2);

    cudaFuncSetAttribute(gcp_conv_kernel,
                         cudaFuncAttributeMaxDynamicSharedMemorySize, SMEM_BYTES);
    gcp_conv_kernel<<<4096, NTHREADS, SMEM_BYTES>>>(x, b1, b2);

    gcp_mlp_kernel<<<512, 256>>>(C, encw, encb, f1w, f1b, f2w, f2b,
                                 f3w, f3b, f4w, f4b, f5w, f5b, ow, ob, out);
}

// round 9
// speedup vs baseline: 1.8413x; 1.1168x over previous
#include <cuda_runtime.h>
#include <cuda_bf16.h>
#include <cstdint>

// ===========================================================================
// Goal_Conditioned_Policies forward, two-kernel design, 32-warp conv CTA.
// K1 (per-sample CTA, 1024 thr, 1 CTA/SM): conv1+conv2 on HMMA bf16 with
//    direct ldmatrix gather; halo-only zeroing; relu+meanpool -> g_pool.
// K2 (warp-per-sample): MLP + C matvec + softmax in registers via shfl.
// ===========================================================================

#define NTHREADS 1024
#define NVAR     50

// ---- K1 smem byte offsets ----
#define XQ_OFF   0u            // [4 pyx][33][33][16B] = 69,696
#define P_OFF    69696u        // [4 pyx][4 g][17][17][16B] = 73,984
#define B1_OFF   143680u       // conv1 weights [80 k][80 B rows] = 6,400
#define B2_OFF   150080u       // conv2 weights [288 k][144 B rows] = 41,472
#define VEC_OFF  191552u
#define SMEM_BYTES 196096u

#define XQ_REG 17424u          // 33*33*16
#define P_REG  4624u           // 17*17*16

// vec float indices
#define V_B1S  0
#define V_B2S  32
#define V_PP   96        // pool partials [32 warps][32]

__device__ __forceinline__ uint32_t smem_u32(const void* p) {
    uint32_t a;
    asm("{ .reg .u64 t; cvta.to.shared.u64 t, %1; cvt.u32.u64 %0, t; }" : "=r"(a) : "l"(p));
    return a;
}
__device__ __forceinline__ void ldsm_x4(uint32_t* r, uint32_t addr) {
    asm volatile("ldmatrix.sync.aligned.m8n8.x4.shared.b16 {%0,%1,%2,%3}, [%4];"
        : "=r"(r[0]), "=r"(r[1]), "=r"(r[2]), "=r"(r[3]) : "r"(addr));
}
__device__ __forceinline__ void ldsm_x4_t(uint32_t* r, uint32_t addr) {
    asm volatile("ldmatrix.sync.aligned.m8n8.x4.trans.shared.b16 {%0,%1,%2,%3}, [%4];"
        : "=r"(r[0]), "=r"(r[1]), "=r"(r[2]), "=r"(r[3]) : "r"(addr));
}
__device__ __forceinline__ void mma16816(float* d, const uint32_t* a, const uint32_t* b) {
    asm volatile(
        "mma.sync.aligned.m16n8k16.row.col.f32.bf16.bf16.f32 "
        "{%0,%1,%2,%3}, {%4,%5,%6,%7}, {%8,%9}, {%0,%1,%2,%3};"
        : "+f"(d[0]), "+f"(d[1]), "+f"(d[2]), "+f"(d[3])
        : "r"(a[0]), "r"(a[1]), "r"(a[2]), "r"(a[3]), "r"(b[0]), "r"(b[1]));
}
__device__ __forceinline__ uint32_t pack_bf16x2(float lo, float hi) {
    uint32_t r;
    asm("cvt.rn.bf16x2.f32 %0, %1, %2;" : "=r"(r) : "f"(hi), "f"(lo));
    return r;
}

// --- global scratch (static device arrays; rebuilt deterministically) ---
__device__ __align__(16) __nv_bfloat16 g_B1[80 * 40];
__device__ __align__(16) __nv_bfloat16 g_B2[288 * 72];
__device__ __align__(16) float g_pool[4096 * 64];

__global__ void w_prep_kernel(const float* __restrict__ w1, const float* __restrict__ w2) {
    int i = blockIdx.x * blockDim.x + threadIdx.x;
    if (i < 80 * 40) {
        int kk = i / 40, slot = i - kk * 40;
        int tap = kk >> 3, j = kk & 7;
        float v = 0.f;
        if (slot < 32 && j < 3 && kk < 72)
            v = w1[slot * 27 + j * 9 + tap];    // w1[oc][ic=j][tap]
        g_B1[i] = __float2bfloat16(v);
    }
    int i2 = i - 80 * 40;
    if (i2 >= 0 && i2 < 288 * 72) {
        int kk = i2 / 72, slot = i2 - kk * 72;
        int tap = kk >> 5, ic = kk & 31;
        float v = (slot < 64) ? w2[(slot * 32 + ic) * 9 + tap] : 0.f;
        g_B2[i2] = __float2bfloat16(v);
    }
}

// ===========================================================================
// K1: convs + pool (1024 threads, 32 warps)
// ===========================================================================
__global__ __launch_bounds__(NTHREADS, 1)
void gcp_conv_kernel(const float* __restrict__ x,
                     const float* __restrict__ b1, const float* __restrict__ b2)
{
    extern __shared__ char smc[];
    const uint32_t smaddr = smem_u32(smc);
    const int b    = blockIdx.x;
    const int tid  = threadIdx.x;
    const int wrp  = tid >> 5;
    const int lane = tid & 31;
    float* vec = (float*)(smc + VEC_OFF);

    // ---- stage: halo-zero XQ+P, copy B1/B2, biases ----
    {
        uint4 z = make_uint4(0, 0, 0, 0);
        // XQ halos: rows iy in {0,32}, cols ix in {0,32}, all 4 parities.
        for (int i = tid; i < 528; i += NTHREADS) {
            int p = i / 132, r = i - p * 132;
            int iy, ix;
            if (r < 66) { iy = (r < 33) ? 0 : 32; ix = (r < 33) ? r : r - 33; }
            else        { int rr = r - 66; ix = (rr < 33) ? 0 : 32; iy = (rr < 33) ? rr : rr - 33; }
            *(uint4*)(smc + XQ_OFF + (uint32_t)p * XQ_REG + (uint32_t)(iy * 33 + ix) * 16u) = z;
        }
        // P halos: per (pyx,g): row iy_h(py) + col ix_h(px).
        for (int i = tid; i < 544; i += NTHREADS) {
            int c = i / 34, r = i - c * 34;
            int pyx = c >> 2, g = c & 3;
            int py = pyx >> 1, px = pyx & 1;
            int iy_h = (py == 0) ? 0 : 16;
            int ix_h = (px == 0) ? 0 : 16;
            int iy, ix;
            if (r < 17) { iy = iy_h; ix = r; }
            else        { iy = r - 17; ix = ix_h; }
            *(uint4*)(smc + P_OFF + (uint32_t)(pyx * 4 + g) * P_REG
                      + (uint32_t)(iy * 17 + ix) * 16u) = z;
        }
        const uint4* gb1 = (const uint4*)g_B1;
        for (int i = tid; i < 400; i += NTHREADS)
            ((uint4*)(smc + B1_OFF))[i] = gb1[i];
        const uint4* gb2 = (const uint4*)g_B2;
        for (int i = tid; i < 2592; i += NTHREADS)
            ((uint4*)(smc + B2_OFF))[i] = gb2[i];
        if (tid < 32) vec[V_B1S + tid] = b1[tid];
        else if (tid < 96) vec[V_B2S + tid - 32] = b2[tid - 32];
    }

    // ---- x -> XQ bf16 parity pixels (full 16B per pixel, pads zeroed) ----
    {
        const float* xb = x + (size_t)b * 12288;
        #pragma unroll
        for (int it = 0; it < 4; it++) {
            int i = it * NTHREADS + tid;            // pixel index 0..4095
            float v0 = xb[i];
            float v1 = xb[4096 + i];
            float v2 = xb[8192 + i];
            uint4 q;
            q.x = pack_bf16x2(v0, v1);
            q.y = pack_bf16x2(v2, 0.f);
            q.z = 0u; q.w = 0u;
            int Y = (i >> 6) + 1, X = (i & 63) + 1;
            uint32_t off = XQ_OFF + (uint32_t)((Y & 1) * 2 + (X & 1)) * XQ_REG
                         + (uint32_t)((Y >> 1) * 33 + (X >> 1)) * 16u;
            *(uint4*)(smc + off) = q;
        }
    }
    __syncthreads();

    const int r8    = lane & 7;
    const int msel  = (lane >> 3) & 1;
    const int khsel = lane >> 4;

    // =====================================================================
    // conv1 GEMM: D1[1024][32], K=80. Warp w: m-tiles {2w, 2w+1}.
    // =====================================================================
    float acc1[2][4][4];
    #pragma unroll
    for (int mt = 0; mt < 2; mt++)
        #pragma unroll
        for (int nt = 0; nt < 4; nt++)
            #pragma unroll
            for (int rg = 0; rg < 4; rg++) acc1[mt][nt][rg] = 0.f;
    {
        #pragma unroll
        for (int ks = 0; ks < 5; ks++) {
            uint32_t bf[2][4];
            {
                uint32_t bb = smaddr + B1_OFF + (uint32_t)(ks * 16 + (lane & 15)) * 80u
                              + (uint32_t)(lane >> 4) * 16u;
                ldsm_x4_t(bf[0], bb);
                ldsm_x4_t(bf[1], bb + 32u);
            }
            const int ta = 2 * ks, tb = 2 * ks + 1;
            const int kya = ta / 3, kxa = ta - 3 * kya;
            const int kyb = (tb < 9) ? tb / 3 : 0, kxb = (tb < 9) ? tb - 3 * kyb : 0;
            #pragma unroll
            for (int mt = 0; mt < 2; mt++) {
                int pos = (wrp * 2 + mt) * 16 + msel * 8 + r8;
                int oy1 = pos >> 5, ox1 = pos & 31;
                uint32_t addr_e = XQ_OFF + (uint32_t)((kya & 1) * 2 + (kxa & 1)) * XQ_REG
                    + (uint32_t)((oy1 + (kya >> 1)) * 33 + ox1 + (kxa >> 1)) * 16u;
                uint32_t addr_o = (tb < 9)
                    ? XQ_OFF + (uint32_t)((kyb & 1) * 2 + (kxb & 1)) * XQ_REG
                      + (uint32_t)((oy1 + (kyb >> 1)) * 33 + ox1 + (kxb >> 1)) * 16u
                    : XQ_OFF;                       // zeroed halo slot (iy=0,ix=0,p=0)
                uint32_t af[4];
                ldsm_x4(af, smaddr + (khsel ? addr_o : addr_e));
                #pragma unroll
                for (int nt = 0; nt < 4; nt++)
                    mma16816(acc1[mt][nt], af, &bf[nt >> 1][(nt & 1) * 2]);
            }
        }
    }

    // ---- writeback: relu(acc1 + b1) -> P ----
    {
        #pragma unroll
        for (int nt = 0; nt < 4; nt++) {
            int n = nt * 8 + (lane & 3) * 2;
            float bb0 = vec[V_B1S + n], bb1 = vec[V_B1S + n + 1];
            uint32_t greg = (uint32_t)(n >> 3) * P_REG;
            uint32_t sub  = (uint32_t)(n & 7) * 2u;
            #pragma unroll
            for (int mt = 0; mt < 2; mt++) {
                #pragma unroll
                for (int hh = 0; hh < 2; hh++) {
                    int pos = (wrp * 2 + mt) * 16 + (lane >> 2) + hh * 8;
                    int Y = (pos >> 5) + 1, X = (pos & 31) + 1;
                    float v0 = fmaxf(acc1[mt][nt][hh * 2 + 0] + bb0, 0.f);
                    float v1 = fmaxf(acc1[mt][nt][hh * 2 + 1] + bb1, 0.f);
                    uint32_t off = P_OFF + (uint32_t)((Y & 1) * 2 + (X & 1)) * (4u * P_REG)
                        + greg + (uint32_t)((Y >> 1) * 17 + (X >> 1)) * 16u + sub;
                    *(uint32_t*)(smc + off) = pack_bf16x2(v0, v1);
                }
            }
        }
    }
    __syncthreads();

    // =====================================================================
    // conv2 GEMM: D2[256][64]. Warp w: m-tile (w&15), n-half (w>>4).
    // =====================================================================
    const int mt2 = wrp & 15;
    const int nh  = wrp >> 4;
    float acc2[4][4];
    {
        #pragma unroll
        for (int jl = 0; jl < 4; jl++) {
            int oc = nh * 32 + jl * 8 + (lane & 3) * 2;
            float b0  = vec[V_B2S + oc];
            float b1v = vec[V_B2S + oc + 1];
            acc2[jl][0] = b0;  acc2[jl][1] = b1v;
            acc2[jl][2] = b0;  acc2[jl][3] = b1v;
        }
    }
    {
        const int ox2 = msel * 8 + r8;
        #pragma unroll
        for (int tap = 0; tap < 9; tap++) {
            const int ky = tap / 3, kx = tap - 3 * ky;
            const uint32_t pbase = P_OFF + (uint32_t)((ky & 1) * 2 + (kx & 1)) * (4u * P_REG)
                + (uint32_t)khsel * P_REG + (uint32_t)(ox2 + (kx >> 1)) * 16u
                + (uint32_t)((mt2 + (ky >> 1)) * 17) * 16u;
            #pragma unroll
            for (int gh = 0; gh < 2; gh++) {
                uint32_t af[4];
                ldsm_x4(af, smaddr + pbase + (uint32_t)gh * (2u * P_REG));
                uint32_t bf[2][4];
                uint32_t bb = smaddr + B2_OFF
                    + (uint32_t)((tap * 32 + gh * 16) + (lane & 15)) * 144u
                    + (uint32_t)(lane >> 4) * 16u + (uint32_t)(2 * nh) * 32u;
                ldsm_x4_t(bf[0], bb);
                ldsm_x4_t(bf[1], bb + 32u);
                #pragma unroll
                for (int jl = 0; jl < 4; jl++)
                    mma16816(acc2[jl], af, &bf[jl >> 1][(jl & 1) * 2]);
            }
        }
    }

    // ---- relu + meanpool from fragments ----
    {
        #pragma unroll
        for (int jl = 0; jl < 4; jl++) {
            float s0 = fmaxf(acc2[jl][0], 0.f) + fmaxf(acc2[jl][2], 0.f);
            float s1 = fmaxf(acc2[jl][1], 0.f) + fmaxf(acc2[jl][3], 0.f);
            s0 += __shfl_xor_sync(0xffffffffu, s0, 4);
            s1 += __shfl_xor_sync(0xffffffffu, s1, 4);
            s0 += __shfl_xor_sync(0xffffffffu, s0, 8);
            s1 += __shfl_xor_sync(0xffffffffu, s1, 8);
            s0 += __shfl_xor_sync(0xffffffffu, s0, 16);
            s1 += __shfl_xor_sync(0xffffffffu, s1, 16);
            if (lane < 4) {
                vec[V_PP + wrp * 32 + jl * 8 + lane * 2]     = s0;
                vec[V_PP + wrp * 32 + jl * 8 + lane * 2 + 1] = s1;
            }
        }
    }
    __syncthreads();
    if (tid < 64) {
        int nhh = tid >> 5, oc32 = tid & 31;
        float s = 0.f;
        #pragma unroll
        for (int mp = 0; mp < 16; mp++)
            s += vec[V_PP + (nhh * 16 + mp) * 32 + oc32];
        g_pool[b * 64 + nhh * 32 + oc32] = s * (1.f / 256.f);
    }
}

// ===========================================================================
// K2: warp-per-sample MLP + C matvec + softmax. No smem, no barriers.
// ===========================================================================
__global__ __launch_bounds__(256, 4)
void gcp_mlp_kernel(const float* __restrict__ C,
                    const float* __restrict__ encw, const float* __restrict__ encb,
                    const float* __restrict__ f1w,  const float* __restrict__ f1b,
                    const float* __restrict__ f2w,  const float* __restrict__ f2b,
                    const float* __restrict__ f3w,  const float* __restrict__ f3b,
                    const float* __restrict__ f4w,  const float* __restrict__ f4b,
                    const float* __restrict__ f5w,  const float* __restrict__ f5b,
                    const float* __restrict__ ow,   const float* __restrict__ ob,
                    float* __restrict__ out)
{
    const int s    = blockIdx.x * 8 + (threadIdx.x >> 5);
    const int lane = threadIdx.x & 31;
    const unsigned FULL = 0xffffffffu;

    const float p0 = g_pool[s * 64 + lane];
    const float p1 = g_pool[s * 64 + 32 + lane];

    float x1r[4];
    #pragma unroll
    for (int j = 0; j < 4; j++) x1r[j] = encb[lane + 32 * j];
    #pragma unroll 4
    for (int k = 0; k < 64; k++) {
        float v = (k < 32) ? __shfl_sync(FULL, p0, k) : __shfl_sync(FULL, p1, k - 32);
        #pragma unroll
        for (int j = 0; j < 4; j++)
            x1r[j] = fmaf(v, __ldg(&encw[k * 128 + lane + 32 * j]), x1r[j]);
    }
    #pragma unroll
    for (int j = 0; j < 4; j++) x1r[j] = fmaxf(x1r[j], 0.f);

    float a0 = f1b[lane];
    float a1 = (lane < 18) ? f1b[lane + 32] : 0.f;
    const int nc = (lane < 18) ? lane + 32 : 49;
    #pragma unroll 4
    for (int k = 0; k < 128; k++) {
        float v = __shfl_sync(FULL, x1r[k >> 5], k & 31);
        a0 = fmaf(v, __ldg(&f1w[k * NVAR + lane]), a0);
        a1 = fmaf(v, __ldg(&f1w[k * NVAR + nc]), a1);
    }
    float x2a = fmaxf(a0, 0.f);
    float x2b = fmaxf(a1, 0.f);

    float ea = 0.f, eb = 0.f;
    {
        const float* cs = C + (size_t)s * 2500;
        for (int n = 0; n < NVAR; n++) {
            float t = __ldg(&cs[n * NVAR + lane]) * x2a;
            if (lane < 18) t = fmaf(__ldg(&cs[n * NVAR + 32 + lane]), x2b, t);
            #pragma unroll
            for (int off = 16; off > 0; off >>= 1)
                t += __shfl_xor_sync(FULL, t, off);
            if (n < 32) { if (lane == n) ea = t; }
            else        { if (lane == n - 32) eb = t; }
        }
    }

    float x3r[4];
    #pragma unroll
    for (int j = 0; j < 4; j++) x3r[j] = f2b[lane + 32 * j];
    #pragma unroll 2
    for (int k = 0; k < NVAR; k++) {
        float v = (k < 32) ? __shfl_sync(FULL, ea, k) : __shfl_sync(FULL, eb, k - 32);
        #pragma unroll
        for (int j = 0; j < 4; j++)
            x3r[j] = fmaf(v, __ldg(&f2w[k * 128 + lane + 32 * j]), x3r[j]);
    }
    #pragma unroll
    for (int j = 0; j < 4; j++) x3r[j] = fmaxf(x3r[j], 0.f);

    float b0 = f3b[lane], b1v = f3b[lane + 32];
    #pragma unroll 4
    for (int k = 0; k < 256; k++) {
        float v = (k < 128) ? __shfl_sync(FULL, x1r[k >> 5], k & 31)
                            : __shfl_sync(FULL, x3r[(k - 128) >> 5], (k - 128) & 31);
        b0  = fmaf(v, __ldg(&f3w[k * 64 + lane]), b0);
        b1v = fmaf(v, __ldg(&f3w[k * 64 + lane + 32]), b1v);
    }
    float x5a = fmaxf(b0, 0.f), x5b = fmaxf(b1v, 0.f);

    float c0 = f4b[lane], c1 = f4b[lane + 32];
    #pragma unroll 4
    for (int k = 0; k < 64; k++) {
        float v = (k < 32) ? __shfl_sync(FULL, x5a, k) : __shfl_sync(FULL, x5b, k - 32);
        c0 = fmaf(v, __ldg(&f4w[k * 64 + lane]), c0);
        c1 = fmaf(v, __ldg(&f4w[k * 64 + lane + 32]), c1);
    }
    float x6a = fmaxf(c0, 0.f), x6b = fmaxf(c1, 0.f);

    float d0 = f5b[lane], d1 = f5b[lane + 32];
    #pragma unroll 4
    for (int k = 0; k < 64; k++) {
        float v = (k < 32) ? __shfl_sync(FULL, x6a, k) : __shfl_sync(FULL, x6b, k - 32);
        d0 = fmaf(v, __ldg(&f5w[k * 64 + lane]), d0);
        d1 = fmaf(v, __ldg(&f5w[k * 64 + lane + 32]), d1);
    }
    float x7a = fmaxf(d0, 0.f), x7b = fmaxf(d1, 0.f);

    float l0 = ob[lane];
    float l1 = (lane < 18) ? ob[lane + 32] : 0.f;
    #pragma unroll 4
    for (int k = 0; k < 64; k++) {
        float v = (k < 32) ? __shfl_sync(FULL, x7a, k) : __shfl_sync(FULL, x7b, k - 32);
        l0 = fmaf(v, __ldg(&ow[k * NVAR + lane]), l0);
        l1 = fmaf(v, __ldg(&ow[k * NVAR + nc]), l1);
    }
    l0 = fmaxf(l0, 0.f);
    l1 = (lane < 18) ? fmaxf(l1, 0.f) : -1e30f;

    float m = fmaxf(l0, l1);
    #pragma unroll
    for (int off = 16; off > 0; off >>= 1)
        m = fmaxf(m, __shfl_xor_sync(FULL, m, off));
    float e0 = expf(l0 - m);
    float e1 = (lane < 18) ? expf(l1 - m) : 0.f;
    float ssum = e0 + e1;
    #pragma unroll
    for (int off = 16; off > 0; off >>= 1)
        ssum += __shfl_xor_sync(FULL, ssum, off);
    float inv = 1.f / ssum;
    out[s * NVAR + lane] = e0 * inv;
    if (lane < 18) out[s * NVAR + 32 + lane] = e1 * inv;
}

extern "C" void kernel_launch(void* const* d_in, const int* in_sizes, int n_in,
                              void* d_out, int out_size)
{
    (void)in_sizes; (void)n_in; (void)out_size;
    const float* x    = (const float*)d_in[0];
    const float* C    = (const float*)d_in[1];
    const float* w1   = (const float*)d_in[2];
    const float* b1   = (const float*)d_in[3];
    const float* w2   = (const float*)d_in[4];
    const float* b2   = (const float*)d_in[5];
    const float* encw = (const float*)d_in[6];
    const float* encb = (const float*)d_in[7];
    const float* f1w  = (const float*)d_in[8];
    const float* f1b  = (const float*)d_in[9];
    const float* f2w  = (const float*)d_in[10];
    const float* f2b  = (const float*)d_in[11];
    const float* f3w  = (const float*)d_in[12];
    const float* f3b  = (const float*)d_in[13];
    const float* f4w  = (const float*)d_in[14];
    const float* f4b  = (const float*)d_in[15];
    const float* f5w  = (const float*)d_in[16];
    const float* f5b  = (const float*)d_in[17];
    const float* ow   = (const float*)d_in[18];
    const float* ob   = (const float*)d_in[19];
    float* out = (float*)d_out;

    w_prep_kernel<<<94, 256>>>(w1, w2);

    cudaFuncSetAttribute(gcp_conv_kernel,
                         cudaFuncAttributeMaxDynamicSharedMemorySize, SMEM_BYTES);
    gcp_conv_kernel<<<4096, NTHREADS, SMEM_BYTES>>>(x, b1, b2);

    gcp_mlp_kernel<<<512, 256>>>(C, encw, encb, f1w, f1b, f2w, f2b,
                                 f3w, f3b, f4w, f4b, f5w, f5b, ow, ob, out);
}

// round 10
// speedup vs baseline: 1.9392x; 1.0532x over previous
#include <cuda_runtime.h>
#include <cuda_bf16.h>
#include <cstdint>

// ===========================================================================
// Goal_Conditioned_Policies forward, persistent-CTA conv + warp-per-sample MLP.
// K1: one CTA per SM (1024 thr), grid-strides over samples. Weights/halos
//     stay resident in smem; per sample only XQ restage + conv1 + conv2 + pool.
// K2: warp-per-sample MLP + C matvec + softmax in registers via shfl.
// ===========================================================================

#define NTHREADS  1024
#define NVAR      50
#define B_SAMPLES 4096

// ---- K1 smem byte offsets ----
#define XQ_OFF   0u            // [4 pyx][33][33][16B] = 69,696
#define P_OFF    69696u        // [4 pyx][4 g][17][17][16B] = 73,984
#define B1_OFF   143680u       // conv1 weights [80 k][80 B rows] = 6,400
#define B2_OFF   150080u       // conv2 weights [288 k][144 B rows] = 41,472
#define VEC_OFF  191552u
#define SMEM_BYTES 196096u

#define XQ_REG 17424u          // 33*33*16
#define P_REG  4624u           // 17*17*16

// vec float indices
#define V_B1S  0
#define V_B2S  32
#define V_PP   96        // pool partials [32 warps][32]

__device__ __forceinline__ uint32_t smem_u32(const void* p) {
    uint32_t a;
    asm("{ .reg .u64 t; cvta.to.shared.u64 t, %1; cvt.u32.u64 %0, t; }" : "=r"(a) : "l"(p));
    return a;
}
__device__ __forceinline__ void ldsm_x4(uint32_t* r, uint32_t addr) {
    asm volatile("ldmatrix.sync.aligned.m8n8.x4.shared.b16 {%0,%1,%2,%3}, [%4];"
        : "=r"(r[0]), "=r"(r[1]), "=r"(r[2]), "=r"(r[3]) : "r"(addr));
}
__device__ __forceinline__ void ldsm_x4_t(uint32_t* r, uint32_t addr) {
    asm volatile("ldmatrix.sync.aligned.m8n8.x4.trans.shared.b16 {%0,%1,%2,%3}, [%4];"
        : "=r"(r[0]), "=r"(r[1]), "=r"(r[2]), "=r"(r[3]) : "r"(addr));
}
__device__ __forceinline__ void mma16816(float* d, const uint32_t* a, const uint32_t* b) {
    asm volatile(
        "mma.sync.aligned.m16n8k16.row.col.f32.bf16.bf16.f32 "
        "{%0,%1,%2,%3}, {%4,%5,%6,%7}, {%8,%9}, {%0,%1,%2,%3};"
        : "+f"(d[0]), "+f"(d[1]), "+f"(d[2]), "+f"(d[3])
        : "r"(a[0]), "r"(a[1]), "r"(a[2]), "r"(a[3]), "r"(b[0]), "r"(b[1]));
}
__device__ __forceinline__ uint32_t pack_bf16x2(float lo, float hi) {
    uint32_t r;
    asm("cvt.rn.bf16x2.f32 %0, %1, %2;" : "=r"(r) : "f"(hi), "f"(lo));
    return r;
}

// --- global scratch (static device arrays; rebuilt deterministically) ---
__device__ __align__(16) __nv_bfloat16 g_B1[80 * 40];
__device__ __align__(16) __nv_bfloat16 g_B2[288 * 72];
__device__ __align__(16) float g_pool[B_SAMPLES * 64];

__global__ void w_prep_kernel(const float* __restrict__ w1, const float* __restrict__ w2) {
    int i = blockIdx.x * blockDim.x + threadIdx.x;
    if (i < 80 * 40) {
        int kk = i / 40, slot = i - kk * 40;
        int tap = kk >> 3, j = kk & 7;
        float v = 0.f;
        if (slot < 32 && j < 3 && kk < 72)
            v = w1[slot * 27 + j * 9 + tap];    // w1[oc][ic=j][tap]
        g_B1[i] = __float2bfloat16(v);
    }
    int i2 = i - 80 * 40;
    if (i2 >= 0 && i2 < 288 * 72) {
        int kk = i2 / 72, slot = i2 - kk * 72;
        int tap = kk >> 5, ic = kk & 31;
        float v = (slot < 64) ? w2[(slot * 32 + ic) * 9 + tap] : 0.f;
        g_B2[i2] = __float2bfloat16(v);
    }
}

__device__ __forceinline__ void stage_xq(char* smc, int tid, const float* __restrict__ x, int s) {
    const float* xb = x + (size_t)s * 12288;
    #pragma unroll
    for (int it = 0; it < 4; it++) {
        int i = it * NTHREADS + tid;            // pixel index 0..4095
        float v0 = xb[i];
        float v1 = xb[4096 + i];
        float v2 = xb[8192 + i];
        uint4 q;
        q.x = pack_bf16x2(v0, v1);
        q.y = pack_bf16x2(v2, 0.f);
        q.z = 0u; q.w = 0u;
        int Y = (i >> 6) + 1, X = (i & 63) + 1;
        uint32_t off = XQ_OFF + (uint32_t)((Y & 1) * 2 + (X & 1)) * XQ_REG
                     + (uint32_t)((Y >> 1) * 33 + (X >> 1)) * 16u;
        *(uint4*)(smc + off) = q;
    }
}

// ===========================================================================
// K1: persistent convs + pool (1024 threads, 32 warps, 1 CTA/SM)
// ===========================================================================
__global__ __launch_bounds__(NTHREADS, 1)
void gcp_conv_kernel(const float* __restrict__ x,
                     const float* __restrict__ b1, const float* __restrict__ b2)
{
    extern __shared__ char smc[];
    const uint32_t smaddr = smem_u32(smc);
    const int tid  = threadIdx.x;
    const int wrp  = tid >> 5;
    const int lane = tid & 31;
    float* vec = (float*)(smc + VEC_OFF);

    // ---- one-time setup: halo-zero XQ+P, copy B1/B2, biases ----
    {
        uint4 z = make_uint4(0, 0, 0, 0);
        for (int i = tid; i < 528; i += NTHREADS) {
            int p = i / 132, r = i - p * 132;
            int iy, ix;
            if (r < 66) { iy = (r < 33) ? 0 : 32; ix = (r < 33) ? r : r - 33; }
            else        { int rr = r - 66; ix = (rr < 33) ? 0 : 32; iy = (rr < 33) ? rr : rr - 33; }
            *(uint4*)(smc + XQ_OFF + (uint32_t)p * XQ_REG + (uint32_t)(iy * 33 + ix) * 16u) = z;
        }
        for (int i = tid; i < 544; i += NTHREADS) {
            int c = i / 34, r = i - c * 34;
            int pyx = c >> 2, g = c & 3;
            int py = pyx >> 1, px = pyx & 1;
            int iy_h = (py == 0) ? 0 : 16;
            int ix_h = (px == 0) ? 0 : 16;
            int iy, ix;
            if (r < 17) { iy = iy_h; ix = r; }
            else        { iy = r - 17; ix = ix_h; }
            *(uint4*)(smc + P_OFF + (uint32_t)(pyx * 4 + g) * P_REG
                      + (uint32_t)(iy * 17 + ix) * 16u) = z;
        }
        const uint4* gb1 = (const uint4*)g_B1;
        for (int i = tid; i < 400; i += NTHREADS)
            ((uint4*)(smc + B1_OFF))[i] = gb1[i];
        const uint4* gb2 = (const uint4*)g_B2;
        for (int i = tid; i < 2592; i += NTHREADS)
            ((uint4*)(smc + B2_OFF))[i] = gb2[i];
        if (tid < 32) vec[V_B1S + tid] = b1[tid];
        else if (tid < 96) vec[V_B2S + tid - 32] = b2[tid - 32];
    }
    // peel: stage first sample
    if ((int)blockIdx.x < B_SAMPLES) stage_xq(smc, tid, x, blockIdx.x);
    __syncthreads();

    const int r8    = lane & 7;
    const int msel  = (lane >> 3) & 1;
    const int khsel = lane >> 4;
    const int mt2   = wrp & 15;
    const int nh    = wrp >> 4;
    const int stride = gridDim.x;

    for (int s = blockIdx.x; s < B_SAMPLES; s += stride) {
        // =================================================================
        // conv1 GEMM: D1[1024][32], K=80. Warp w: m-tiles {2w, 2w+1}.
        // =================================================================
        float acc1[2][4][4];
        #pragma unroll
        for (int mt = 0; mt < 2; mt++)
            #pragma unroll
            for (int nt = 0; nt < 4; nt++)
                #pragma unroll
                for (int rg = 0; rg < 4; rg++) acc1[mt][nt][rg] = 0.f;
        {
            #pragma unroll
            for (int ks = 0; ks < 5; ks++) {
                uint32_t bf[2][4];
                {
                    uint32_t bb = smaddr + B1_OFF + (uint32_t)(ks * 16 + (lane & 15)) * 80u
                                  + (uint32_t)(lane >> 4) * 16u;
                    ldsm_x4_t(bf[0], bb);
                    ldsm_x4_t(bf[1], bb + 32u);
                }
                const int ta = 2 * ks, tb = 2 * ks + 1;
                const int kya = ta / 3, kxa = ta - 3 * kya;
                const int kyb = (tb < 9) ? tb / 3 : 0, kxb = (tb < 9) ? tb - 3 * kyb : 0;
                #pragma unroll
                for (int mt = 0; mt < 2; mt++) {
                    int pos = (wrp * 2 + mt) * 16 + msel * 8 + r8;
                    int oy1 = pos >> 5, ox1 = pos & 31;
                    uint32_t addr_e = XQ_OFF + (uint32_t)((kya & 1) * 2 + (kxa & 1)) * XQ_REG
                        + (uint32_t)((oy1 + (kya >> 1)) * 33 + ox1 + (kxa >> 1)) * 16u;
                    uint32_t addr_o = (tb < 9)
                        ? XQ_OFF + (uint32_t)((kyb & 1) * 2 + (kxb & 1)) * XQ_REG
                          + (uint32_t)((oy1 + (kyb >> 1)) * 33 + ox1 + (kxb >> 1)) * 16u
                        : XQ_OFF;                       // zeroed halo slot
                    uint32_t af[4];
                    ldsm_x4(af, smaddr + (khsel ? addr_o : addr_e));
                    #pragma unroll
                    for (int nt = 0; nt < 4; nt++)
                        mma16816(acc1[mt][nt], af, &bf[nt >> 1][(nt & 1) * 2]);
                }
            }
        }
        // ---- writeback: relu(acc1 + b1) -> P ----
        {
            #pragma unroll
            for (int nt = 0; nt < 4; nt++) {
                int n = nt * 8 + (lane & 3) * 2;
                float bb0 = vec[V_B1S + n], bb1 = vec[V_B1S + n + 1];
                uint32_t greg = (uint32_t)(n >> 3) * P_REG;
                uint32_t sub  = (uint32_t)(n & 7) * 2u;
                #pragma unroll
                for (int mt = 0; mt < 2; mt++) {
                    #pragma unroll
                    for (int hh = 0; hh < 2; hh++) {
                        int pos = (wrp * 2 + mt) * 16 + (lane >> 2) + hh * 8;
                        int Y = (pos >> 5) + 1, X = (pos & 31) + 1;
                        float v0 = fmaxf(acc1[mt][nt][hh * 2 + 0] + bb0, 0.f);
                        float v1 = fmaxf(acc1[mt][nt][hh * 2 + 1] + bb1, 0.f);
                        uint32_t off = P_OFF + (uint32_t)((Y & 1) * 2 + (X & 1)) * (4u * P_REG)
                            + greg + (uint32_t)((Y >> 1) * 17 + (X >> 1)) * 16u + sub;
                        *(uint32_t*)(smc + off) = pack_bf16x2(v0, v1);
                    }
                }
            }
        }
        __syncthreads();   // A: P ready; conv1's XQ reads done

        // ---- stage next sample's XQ (overlaps with conv2 below) ----
        int sn = s + stride;
        if (sn < B_SAMPLES) stage_xq(smc, tid, x, sn);

        // =================================================================
        // conv2 GEMM: D2[256][64]. Warp w: m-tile (w&15), n-half (w>>4).
        // =================================================================
        float acc2[4][4];
        {
            #pragma unroll
            for (int jl = 0; jl < 4; jl++) {
                int oc = nh * 32 + jl * 8 + (lane & 3) * 2;
                float b0  = vec[V_B2S + oc];
                float b1v = vec[V_B2S + oc + 1];
                acc2[jl][0] = b0;  acc2[jl][1] = b1v;
                acc2[jl][2] = b0;  acc2[jl][3] = b1v;
            }
        }
        {
            const int ox2 = msel * 8 + r8;
            #pragma unroll
            for (int tap = 0; tap < 9; tap++) {
                const int ky = tap / 3, kx = tap - 3 * ky;
                const uint32_t pbase = P_OFF
                    + (uint32_t)((ky & 1) * 2 + (kx & 1)) * (4u * P_REG)
                    + (uint32_t)khsel * P_REG + (uint32_t)(ox2 + (kx >> 1)) * 16u
                    + (uint32_t)((mt2 + (ky >> 1)) * 17) * 16u;
                #pragma unroll
                for (int gh = 0; gh < 2; gh++) {
                    uint32_t af[4];
                    ldsm_x4(af, smaddr + pbase + (uint32_t)gh * (2u * P_REG));
                    uint32_t bf[2][4];
                    uint32_t bb = smaddr + B2_OFF
                        + (uint32_t)((tap * 32 + gh * 16) + (lane & 15)) * 144u
                        + (uint32_t)(lane >> 4) * 16u + (uint32_t)(2 * nh) * 32u;
                    ldsm_x4_t(bf[0], bb);
                    ldsm_x4_t(bf[1], bb + 32u);
                    #pragma unroll
                    for (int jl = 0; jl < 4; jl++)
                        mma16816(acc2[jl], af, &bf[jl >> 1][(jl & 1) * 2]);
                }
            }
        }
        // ---- relu + meanpool partials ----
        {
            #pragma unroll
            for (int jl = 0; jl < 4; jl++) {
                float s0 = fmaxf(acc2[jl][0], 0.f) + fmaxf(acc2[jl][2], 0.f);
                float s1 = fmaxf(acc2[jl][1], 0.f) + fmaxf(acc2[jl][3], 0.f);
                s0 += __shfl_xor_sync(0xffffffffu, s0, 4);
                s1 += __shfl_xor_sync(0xffffffffu, s1, 4);
                s0 += __shfl_xor_sync(0xffffffffu, s0, 8);
                s1 += __shfl_xor_sync(0xffffffffu, s1, 8);
                s0 += __shfl_xor_sync(0xffffffffu, s0, 16);
                s1 += __shfl_xor_sync(0xffffffffu, s1, 16);
                if (lane < 4) {
                    vec[V_PP + wrp * 32 + jl * 8 + lane * 2]     = s0;
                    vec[V_PP + wrp * 32 + jl * 8 + lane * 2 + 1] = s1;
                }
            }
        }
        __syncthreads();   // B: PP ready; XQ(sn) staged for next conv1

        if (tid < 64) {
            int nhh = tid >> 5, oc32 = tid & 31;
            float sacc = 0.f;
            #pragma unroll
            for (int mp = 0; mp < 16; mp++)
                sacc += vec[V_PP + (nhh * 16 + mp) * 32 + oc32];
            g_pool[s * 64 + nhh * 32 + oc32] = sacc * (1.f / 256.f);
        }
        // PP reads complete before any warp passes next iteration's sync A,
        // which precedes the next conv2's PP writes — no extra barrier needed.
    }
}

// ===========================================================================
// K2: warp-per-sample MLP + C matvec + softmax. No smem, no barriers.
// ===========================================================================
__global__ __launch_bounds__(256, 4)
void gcp_mlp_kernel(const float* __restrict__ C,
                    const float* __restrict__ encw, const float* __restrict__ encb,
                    const float* __restrict__ f1w,  const float* __restrict__ f1b,
                    const float* __restrict__ f2w,  const float* __restrict__ f2b,
                    const float* __restrict__ f3w,  const float* __restrict__ f3b,
                    const float* __restrict__ f4w,  const float* __restrict__ f4b,
                    const float* __restrict__ f5w,  const float* __restrict__ f5b,
                    const float* __restrict__ ow,   const float* __restrict__ ob,
                    float* __restrict__ out)
{
    const int s    = blockIdx.x * 8 + (threadIdx.x >> 5);
    const int lane = threadIdx.x & 31;
    const unsigned FULL = 0xffffffffu;

    const float p0 = g_pool[s * 64 + lane];
    const float p1 = g_pool[s * 64 + 32 + lane];

    float x1r[4];
    #pragma unroll
    for (int j = 0; j < 4; j++) x1r[j] = encb[lane + 32 * j];
    #pragma unroll 4
    for (int k = 0; k < 64; k++) {
        float v = (k < 32) ? __shfl_sync(FULL, p0, k) : __shfl_sync(FULL, p1, k - 32);
        #pragma unroll
        for (int j = 0; j < 4; j++)
            x1r[j] = fmaf(v, __ldg(&encw[k * 128 + lane + 32 * j]), x1r[j]);
    }
    #pragma unroll
    for (int j = 0; j < 4; j++) x1r[j] = fmaxf(x1r[j], 0.f);

    float a0 = f1b[lane];
    float a1 = (lane < 18) ? f1b[lane + 32] : 0.f;
    const int nc = (lane < 18) ? lane + 32 : 49;
    #pragma unroll 4
    for (int k = 0; k < 128; k++) {
        float v = __shfl_sync(FULL, x1r[k >> 5], k & 31);
        a0 = fmaf(v, __ldg(&f1w[k * NVAR + lane]), a0);
        a1 = fmaf(v, __ldg(&f1w[k * NVAR + nc]), a1);
    }
    float x2a = fmaxf(a0, 0.f);
    float x2b = fmaxf(a1, 0.f);

    float ea = 0.f, eb = 0.f;
    {
        const float* cs = C + (size_t)s * 2500;
        for (int n = 0; n < NVAR; n++) {
            float t = __ldg(&cs[n * NVAR + lane]) * x2a;
            if (lane < 18) t = fmaf(__ldg(&cs[n * NVAR + 32 + lane]), x2b, t);
            #pragma unroll
            for (int off = 16; off > 0; off >>= 1)
                t += __shfl_xor_sync(FULL, t, off);
            if (n < 32) { if (lane == n) ea = t; }
            else        { if (lane == n - 32) eb = t; }
        }
    }

    float x3r[4];
    #pragma unroll
    for (int j = 0; j < 4; j++) x3r[j] = f2b[lane + 32 * j];
    #pragma unroll 2
    for (int k = 0; k < NVAR; k++) {
        float v = (k < 32) ? __shfl_sync(FULL, ea, k) : __shfl_sync(FULL, eb, k - 32);
        #pragma unroll
        for (int j = 0; j < 4; j++)
            x3r[j] = fmaf(v, __ldg(&f2w[k * 128 + lane + 32 * j]), x3r[j]);
    }
    #pragma unroll
    for (int j = 0; j < 4; j++) x3r[j] = fmaxf(x3r[j], 0.f);

    float b0 = f3b[lane], b1v = f3b[lane + 32];
    #pragma unroll 4
    for (int k = 0; k < 256; k++) {
        float v = (k < 128) ? __shfl_sync(FULL, x1r[k >> 5], k & 31)
                            : __shfl_sync(FULL, x3r[(k - 128) >> 5], (k - 128) & 31);
        b0  = fmaf(v, __ldg(&f3w[k * 64 + lane]), b0);
        b1v = fmaf(v, __ldg(&f3w[k * 64 + lane + 32]), b1v);
    }
    float x5a = fmaxf(b0, 0.f), x5b = fmaxf(b1v, 0.f);

    float c0 = f4b[lane], c1 = f4b[lane + 32];
    #pragma unroll 4
    for (int k = 0; k < 64; k++) {
        float v = (k < 32) ? __shfl_sync(FULL, x5a, k) : __shfl_sync(FULL, x5b, k - 32);
        c0 = fmaf(v, __ldg(&f4w[k * 64 + lane]), c0);
        c1 = fmaf(v, __ldg(&f4w[k * 64 + lane + 32]), c1);
    }
    float x6a = fmaxf(c0, 0.f), x6b = fmaxf(c1, 0.f);

    float d0 = f5b[lane], d1 = f5b[lane + 32];
    #pragma unroll 4
    for (int k = 0; k < 64; k++) {
        float v = (k < 32) ? __shfl_sync(FULL, x6a, k) : __shfl_sync(FULL, x6b, k - 32);
        d0 = fmaf(v, __ldg(&f5w[k * 64 + lane]), d0);
        d1 = fmaf(v, __ldg(&f5w[k * 64 + lane + 32]), d1);
    }
    float x7a = fmaxf(d0, 0.f), x7b = fmaxf(d1, 0.f);

    float l0 = ob[lane];
    float l1 = (lane < 18) ? ob[lane + 32] : 0.f;
    #pragma unroll 4
    for (int k = 0; k < 64; k++) {
        float v = (k < 32) ? __shfl_sync(FULL, x7a, k) : __shfl_sync(FULL, x7b, k - 32);
        l0 = fmaf(v, __ldg(&ow[k * NVAR + lane]), l0);
        l1 = fmaf(v, __ldg(&ow[k * NVAR + nc]), l1);
    }
    l0 = fmaxf(l0, 0.f);
    l1 = (lane < 18) ? fmaxf(l1, 0.f) : -1e30f;

    float m = fmaxf(l0, l1);
    #pragma unroll
    for (int off = 16; off > 0; off >>= 1)
        m = fmaxf(m, __shfl_xor_sync(FULL, m, off));
    float e0 = expf(l0 - m);
    float e1 = (lane < 18) ? expf(l1 - m) : 0.f;
    float ssum = e0 + e1;
    #pragma unroll
    for (int off = 16; off > 0; off >>= 1)
        ssum += __shfl_xor_sync(FULL, ssum, off);
    float inv = 1.f / ssum;
    out[s * NVAR + lane] = e0 * inv;
    if (lane < 18) out[s * NVAR + 32 + lane] = e1 * inv;
}

extern "C" void kernel_launch(void* const* d_in, const int* in_sizes, int n_in,
                              void* d_out, int out_size)
{
    (void)in_sizes; (void)n_in; (void)out_size;
    const float* x    = (const float*)d_in[0];
    const float* C    = (const float*)d_in[1];
    const float* w1   = (const float*)d_in[2];
    const float* b1   = (const float*)d_in[3];
    const float* w2   = (const float*)d_in[4];
    const float* b2   = (const float*)d_in[5];
    const float* encw = (const float*)d_in[6];
    const float* encb = (const float*)d_in[7];
    const float* f1w  = (const float*)d_in[8];
    const float* f1b  = (const float*)d_in[9];
    const float* f2w  = (const float*)d_in[10];
    const float* f2b  = (const float*)d_in[11];
    const float* f3w  = (const float*)d_in[12];
    const float* f3b  = (const float*)d_in[13];
    const float* f4w  = (const float*)d_in[14];
    const float* f4b  = (const float*)d_in[15];
    const float* f5w  = (const float*)d_in[16];
    const float* f5b  = (const float*)d_in[17];
    const float* ow   = (const float*)d_in[18];
    const float* ob   = (const float*)d_in[19];
    float* out = (float*)d_out;

    int nsm = 148;
    cudaDeviceGetAttribute(&nsm, cudaDevAttrMultiProcessorCount, 0);

    w_prep_kernel<<<94, 256>>>(w1, w2);

    cudaFuncSetAttribute(gcp_conv_kernel,
                         cudaFuncAttributeMaxDynamicSharedMemorySize, SMEM_BYTES);
    gcp_conv_kernel<<<nsm, NTHREADS, SMEM_BYTES>>>(x, b1, b2);

    gcp_mlp_kernel<<<B_SAMPLES / 8, 256>>>(C, encw, encb, f1w, f1b, f2w, f2b,
                                           f3w, f3b, f4w, f4b, f5w, f5b, ow, ob, out);
}

// round 11
// speedup vs baseline: 1.9989x; 1.0308x over previous
#include <cuda_runtime.h>
#include <cuda_bf16.h>
#include <cstdint>

// ===========================================================================
// Goal_Conditioned_Policies forward, persistent-CTA conv + warp-per-sample MLP.
// K1: one CTA per SM (1024 thr), grid-strides over samples. Weights/halos
//     resident in smem; conv2 software-pipelined (double-buffered fragments).
// K2: warp-per-sample MLP + C matvec + softmax in registers via shfl.
// ===========================================================================

#define NTHREADS  1024
#define NVAR      50
#define B_SAMPLES 4096

// ---- K1 smem byte offsets ----
#define XQ_OFF   0u            // [4 pyx][33][33][16B] = 69,696
#define P_OFF    69696u        // [4 pyx][4 g][17][17][16B] = 73,984
#define B1_OFF   143680u       // conv1 weights [80 k][80 B rows] = 6,400
#define B2_OFF   150080u       // conv2 weights [288 k][144 B rows] = 41,472
#define VEC_OFF  191552u
#define SMEM_BYTES 196096u

#define XQ_REG 17424u          // 33*33*16
#define P_REG  4624u           // 17*17*16

// vec float indices
#define V_B1S  0
#define V_B2S  32
#define V_PP   96        // pool partials [32 warps][32]

__device__ __forceinline__ uint32_t smem_u32(const void* p) {
    uint32_t a;
    asm("{ .reg .u64 t; cvta.to.shared.u64 t, %1; cvt.u32.u64 %0, t; }" : "=r"(a) : "l"(p));
    return a;
}
__device__ __forceinline__ void ldsm_x4(uint32_t* r, uint32_t addr) {
    asm volatile("ldmatrix.sync.aligned.m8n8.x4.shared.b16 {%0,%1,%2,%3}, [%4];"
        : "=r"(r[0]), "=r"(r[1]), "=r"(r[2]), "=r"(r[3]) : "r"(addr));
}
__device__ __forceinline__ void ldsm_x4_t(uint32_t* r, uint32_t addr) {
    asm volatile("ldmatrix.sync.aligned.m8n8.x4.trans.shared.b16 {%0,%1,%2,%3}, [%4];"
        : "=r"(r[0]), "=r"(r[1]), "=r"(r[2]), "=r"(r[3]) : "r"(addr));
}
__device__ __forceinline__ void mma16816(float* d, const uint32_t* a, const uint32_t* b) {
    asm volatile(
        "mma.sync.aligned.m16n8k16.row.col.f32.bf16.bf16.f32 "
        "{%0,%1,%2,%3}, {%4,%5,%6,%7}, {%8,%9}, {%0,%1,%2,%3};"
        : "+f"(d[0]), "+f"(d[1]), "+f"(d[2]), "+f"(d[3])
        : "r"(a[0]), "r"(a[1]), "r"(a[2]), "r"(a[3]), "r"(b[0]), "r"(b[1]));
}
__device__ __forceinline__ uint32_t pack_bf16x2(float lo, float hi) {
    uint32_t r;
    asm("cvt.rn.bf16x2.f32 %0, %1, %2;" : "=r"(r) : "f"(hi), "f"(lo));
    return r;
}

// --- global scratch (static device arrays; rebuilt deterministically) ---
__device__ __align__(16) __nv_bfloat16 g_B1[80 * 40];
__device__ __align__(16) __nv_bfloat16 g_B2[288 * 72];
__device__ __align__(16) float g_pool[B_SAMPLES * 64];

__global__ void w_prep_kernel(const float* __restrict__ w1, const float* __restrict__ w2) {
    int i = blockIdx.x * blockDim.x + threadIdx.x;
    if (i < 80 * 40) {
        int kk = i / 40, slot = i - kk * 40;
        int tap = kk >> 3, j = kk & 7;
        float v = 0.f;
        if (slot < 32 && j < 3 && kk < 72)
            v = w1[slot * 27 + j * 9 + tap];    // w1[oc][ic=j][tap]
        g_B1[i] = __float2bfloat16(v);
    }
    int i2 = i - 80 * 40;
    if (i2 >= 0 && i2 < 288 * 72) {
        int kk = i2 / 72, slot = i2 - kk * 72;
        int tap = kk >> 5, ic = kk & 31;
        float v = (slot < 64) ? w2[(slot * 32 + ic) * 9 + tap] : 0.f;
        g_B2[i2] = __float2bfloat16(v);
    }
}

// Stage sample's x into XQ (lower 8B of each interior pixel cell; upper 8B of
// every cell is zeroed once at setup and never overwritten).
__device__ __forceinline__ void stage_xq(char* smc, int tid, const float* __restrict__ x, int s) {
    const float* xb = x + (size_t)s * 12288;
    #pragma unroll
    for (int it = 0; it < 4; it++) {
        int i = it * NTHREADS + tid;            // pixel index 0..4095
        float v0 = xb[i];
        float v1 = xb[4096 + i];
        float v2 = xb[8192 + i];
        uint2 q;
        q.x = pack_bf16x2(v0, v1);
        q.y = pack_bf16x2(v2, 0.f);
        int Y = (i >> 6) + 1, X = (i & 63) + 1;
        uint32_t off = XQ_OFF + (uint32_t)((Y & 1) * 2 + (X & 1)) * XQ_REG
                     + (uint32_t)((Y >> 1) * 33 + (X >> 1)) * 16u;
        *(uint2*)(smc + off) = q;
    }
}

// ===========================================================================
// K1: persistent convs + pool (1024 threads, 32 warps, 1 CTA/SM)
// ===========================================================================
__global__ __launch_bounds__(NTHREADS, 1)
void gcp_conv_kernel(const float* __restrict__ x,
                     const float* __restrict__ b1, const float* __restrict__ b2)
{
    extern __shared__ char smc[];
    const uint32_t smaddr = smem_u32(smc);
    const int tid  = threadIdx.x;
    const int wrp  = tid >> 5;
    const int lane = tid & 31;
    float* vec = (float*)(smc + VEC_OFF);

    // ---- one-time setup: zero FULL XQ (pads + halos), P halos, B1/B2, biases ----
    {
        uint4 z = make_uint4(0, 0, 0, 0);
        for (int i = tid; i < 4356; i += NTHREADS)      // all of XQ (69,696 B)
            ((uint4*)(smc + XQ_OFF))[i] = z;
        for (int i = tid; i < 544; i += NTHREADS) {
            int c = i / 34, r = i - c * 34;
            int pyx = c >> 2, g = c & 3;
            int py = pyx >> 1, px = pyx & 1;
            int iy_h = (py == 0) ? 0 : 16;
            int ix_h = (px == 0) ? 0 : 16;
            int iy, ix;
            if (r < 17) { iy = iy_h; ix = r; }
            else        { iy = r - 17; ix = ix_h; }
            *(uint4*)(smc + P_OFF + (uint32_t)(pyx * 4 + g) * P_REG
                      + (uint32_t)(iy * 17 + ix) * 16u) = z;
        }
        const uint4* gb1 = (const uint4*)g_B1;
        for (int i = tid; i < 400; i += NTHREADS)
            ((uint4*)(smc + B1_OFF))[i] = gb1[i];
        const uint4* gb2 = (const uint4*)g_B2;
        for (int i = tid; i < 2592; i += NTHREADS)
            ((uint4*)(smc + B2_OFF))[i] = gb2[i];
        if (tid < 32) vec[V_B1S + tid] = b1[tid];
        else if (tid < 96) vec[V_B2S + tid - 32] = b2[tid - 32];
    }
    __syncthreads();   // XQ zero must complete before interior staging
    if ((int)blockIdx.x < B_SAMPLES) stage_xq(smc, tid, x, blockIdx.x);
    __syncthreads();

    const int r8    = lane & 7;
    const int msel  = (lane >> 3) & 1;
    const int khsel = lane >> 4;
    const int mt2   = wrp & 15;
    const int nh    = wrp >> 4;
    const int stride = gridDim.x;
    const int ox2   = msel * 8 + r8;

    for (int s = blockIdx.x; s < B_SAMPLES; s += stride) {
        // =================================================================
        // conv1 GEMM: D1[1024][32], K=80. Warp w: m-tiles {2w, 2w+1}.
        // Per ks: all loads (B x2, A x2) hoisted ahead of the 32 mma.
        // =================================================================
        float acc1[2][4][4];
        #pragma unroll
        for (int mt = 0; mt < 2; mt++)
            #pragma unroll
            for (int nt = 0; nt < 4; nt++)
                #pragma unroll
                for (int rg = 0; rg < 4; rg++) acc1[mt][nt][rg] = 0.f;
        {
            #pragma unroll
            for (int ks = 0; ks < 5; ks++) {
                uint32_t bf[2][4];
                uint32_t bb = smaddr + B1_OFF + (uint32_t)(ks * 16 + (lane & 15)) * 80u
                              + (uint32_t)(lane >> 4) * 16u;
                ldsm_x4_t(bf[0], bb);
                ldsm_x4_t(bf[1], bb + 32u);

                const int ta = 2 * ks, tb = 2 * ks + 1;
                const int kya = ta / 3, kxa = ta - 3 * kya;
                const int kyb = (tb < 9) ? tb / 3 : 0, kxb = (tb < 9) ? tb - 3 * kyb : 0;
                uint32_t af[2][4];
                #pragma unroll
                for (int mt = 0; mt < 2; mt++) {
                    int pos = (wrp * 2 + mt) * 16 + msel * 8 + r8;
                    int oy1 = pos >> 5, ox1 = pos & 31;
                    uint32_t addr_e = XQ_OFF + (uint32_t)((kya & 1) * 2 + (kxa & 1)) * XQ_REG
                        + (uint32_t)((oy1 + (kya >> 1)) * 33 + ox1 + (kxa >> 1)) * 16u;
                    uint32_t addr_o = (tb < 9)
                        ? XQ_OFF + (uint32_t)((kyb & 1) * 2 + (kxb & 1)) * XQ_REG
                          + (uint32_t)((oy1 + (kyb >> 1)) * 33 + ox1 + (kxb >> 1)) * 16u
                        : XQ_OFF;                       // zeroed halo slot
                    ldsm_x4(af[mt], smaddr + (khsel ? addr_o : addr_e));
                }
                #pragma unroll
                for (int mt = 0; mt < 2; mt++)
                    #pragma unroll
                    for (int nt = 0; nt < 4; nt++)
                        mma16816(acc1[mt][nt], af[mt], &bf[nt >> 1][(nt & 1) * 2]);
            }
        }
        // ---- writeback: relu(acc1 + b1) -> P ----
        {
            #pragma unroll
            for (int nt = 0; nt < 4; nt++) {
                int n = nt * 8 + (lane & 3) * 2;
                float bb0 = vec[V_B1S + n], bb1 = vec[V_B1S + n + 1];
                uint32_t greg = (uint32_t)(n >> 3) * P_REG;
                uint32_t sub  = (uint32_t)(n & 7) * 2u;
                #pragma unroll
                for (int mt = 0; mt < 2; mt++) {
                    #pragma unroll
                    for (int hh = 0; hh < 2; hh++) {
                        int pos = (wrp * 2 + mt) * 16 + (lane >> 2) + hh * 8;
                        int Y = (pos >> 5) + 1, X = (pos & 31) + 1;
                        float v0 = fmaxf(acc1[mt][nt][hh * 2 + 0] + bb0, 0.f);
                        float v1 = fmaxf(acc1[mt][nt][hh * 2 + 1] + bb1, 0.f);
                        uint32_t off = P_OFF + (uint32_t)((Y & 1) * 2 + (X & 1)) * (4u * P_REG)
                            + greg + (uint32_t)((Y >> 1) * 17 + (X >> 1)) * 16u + sub;
                        *(uint32_t*)(smc + off) = pack_bf16x2(v0, v1);
                    }
                }
            }
        }
        __syncthreads();   // A: P ready; conv1's XQ reads done

        // ---- stage next sample's XQ (overlaps with conv2 below) ----
        int sn = s + stride;
        if (sn < B_SAMPLES) stage_xq(smc, tid, x, sn);

        // =================================================================
        // conv2 GEMM: D2[256][64]. Warp w: m-tile (w&15), n-half (w>>4).
        // 18 stages (tap x gh), software-pipelined double-buffered fragments.
        // =================================================================
        float acc2[4][4];
        {
            #pragma unroll
            for (int jl = 0; jl < 4; jl++) {
                int oc = nh * 32 + jl * 8 + (lane & 3) * 2;
                float b0  = vec[V_B2S + oc];
                float b1v = vec[V_B2S + oc + 1];
                acc2[jl][0] = b0;  acc2[jl][1] = b1v;
                acc2[jl][2] = b0;  acc2[jl][3] = b1v;
            }
        }
        {
            uint32_t af[2][4];
            uint32_t bf[2][2][4];

            // fragment loader for stage st = tap*2 + gh
            #define LD_STAGE(st, buf)                                              \
            do {                                                                   \
                const int _tap = (st) >> 1, _gh = (st) & 1;                        \
                const int _ky = _tap / 3, _kx = _tap - 3 * _ky;                    \
                uint32_t _pb = P_OFF                                               \
                    + (uint32_t)((_ky & 1) * 2 + (_kx & 1)) * (4u * P_REG)         \
                    + (uint32_t)khsel * P_REG                                      \
                    + (uint32_t)(ox2 + (_kx >> 1)) * 16u                           \
                    + (uint32_t)((mt2 + (_ky >> 1)) * 17) * 16u                    \
                    + (uint32_t)_gh * (2u * P_REG);                                \
                ldsm_x4(af[buf], smaddr + _pb);                                    \
                uint32_t _bb = smaddr + B2_OFF                                     \
                    + (uint32_t)((_tap * 32 + _gh * 16) + (lane & 15)) * 144u      \
                    + (uint32_t)(lane >> 4) * 16u + (uint32_t)(2 * nh) * 32u;      \
                ldsm_x4_t(bf[buf][0], _bb);                                        \
                ldsm_x4_t(bf[buf][1], _bb + 32u);                                  \
            } while (0)

            LD_STAGE(0, 0);
            #pragma unroll
            for (int st = 0; st < 18; st++) {
                const int cur = st & 1;
                if (st < 17) LD_STAGE(st + 1, cur ^ 1);
                #pragma unroll
                for (int jl = 0; jl < 4; jl++)
                    mma16816(acc2[jl], af[cur], &bf[cur][jl >> 1][(jl & 1) * 2]);
            }
            #undef LD_STAGE
        }
        // ---- relu + meanpool partials ----
        {
            #pragma unroll
            for (int jl = 0; jl < 4; jl++) {
                float s0 = fmaxf(acc2[jl][0], 0.f) + fmaxf(acc2[jl][2], 0.f);
                float s1 = fmaxf(acc2[jl][1], 0.f) + fmaxf(acc2[jl][3], 0.f);
                s0 += __shfl_xor_sync(0xffffffffu, s0, 4);
                s1 += __shfl_xor_sync(0xffffffffu, s1, 4);
                s0 += __shfl_xor_sync(0xffffffffu, s0, 8);
                s1 += __shfl_xor_sync(0xffffffffu, s1, 8);
                s0 += __shfl_xor_sync(0xffffffffu, s0, 16);
                s1 += __shfl_xor_sync(0xffffffffu, s1, 16);
                if (lane < 4) {
                    vec[V_PP + wrp * 32 + jl * 8 + lane * 2]     = s0;
                    vec[V_PP + wrp * 32 + jl * 8 + lane * 2 + 1] = s1;
                }
            }
        }
        __syncthreads();   // B: PP ready; XQ(sn) staged for next conv1

        if (tid < 64) {
            int nhh = tid >> 5, oc32 = tid & 31;
            float sacc = 0.f;
            #pragma unroll
            for (int mp = 0; mp < 16; mp++)
                sacc += vec[V_PP + (nhh * 16 + mp) * 32 + oc32];
            g_pool[s * 64 + nhh * 32 + oc32] = sacc * (1.f / 256.f);
        }
        // PP reads finish before any warp passes next iteration's sync A,
        // which precedes the next conv2's PP writes — no extra barrier needed.
    }
}

// ===========================================================================
// K2: warp-per-sample MLP + C matvec + softmax. No smem, no barriers.
// ===========================================================================
__global__ __launch_bounds__(256, 4)
void gcp_mlp_kernel(const float* __restrict__ C,
                    const float* __restrict__ encw, const float* __restrict__ encb,
                    const float* __restrict__ f1w,  const float* __restrict__ f1b,
                    const float* __restrict__ f2w,  const float* __restrict__ f2b,
                    const float* __restrict__ f3w,  const float* __restrict__ f3b,
                    const float* __restrict__ f4w,  const float* __restrict__ f4b,
                    const float* __restrict__ f5w,  const float* __restrict__ f5b,
                    const float* __restrict__ ow,   const float* __restrict__ ob,
                    float* __restrict__ out)
{
    const int s    = blockIdx.x * 8 + (threadIdx.x >> 5);
    const int lane = threadIdx.x & 31;
    const unsigned FULL = 0xffffffffu;

    const float p0 = g_pool[s * 64 + lane];
    const float p1 = g_pool[s * 64 + 32 + lane];

    float x1r[4];
    #pragma unroll
    for (int j = 0; j < 4; j++) x1r[j] = encb[lane + 32 * j];
    #pragma unroll 4
    for (int k = 0; k < 64; k++) {
        float v = (k < 32) ? __shfl_sync(FULL, p0, k) : __shfl_sync(FULL, p1, k - 32);
        #pragma unroll
        for (int j = 0; j < 4; j++)
            x1r[j] = fmaf(v, __ldg(&encw[k * 128 + lane + 32 * j]), x1r[j]);
    }
    #pragma unroll
    for (int j = 0; j < 4; j++) x1r[j] = fmaxf(x1r[j], 0.f);

    float a0 = f1b[lane];
    float a1 = (lane < 18) ? f1b[lane + 32] : 0.f;
    const int nc = (lane < 18) ? lane + 32 : 49;
    #pragma unroll 4
    for (int k = 0; k < 128; k++) {
        float v = __shfl_sync(FULL, x1r[k >> 5], k & 31);
        a0 = fmaf(v, __ldg(&f1w[k * NVAR + lane]), a0);
        a1 = fmaf(v, __ldg(&f1w[k * NVAR + nc]), a1);
    }
    float x2a = fmaxf(a0, 0.f);
    float x2b = fmaxf(a1, 0.f);

    float ea = 0.f, eb = 0.f;
    {
        const float* cs = C + (size_t)s * 2500;
        for (int n = 0; n < NVAR; n++) {
            float t = __ldg(&cs[n * NVAR + lane]) * x2a;
            if (lane < 18) t = fmaf(__ldg(&cs[n * NVAR + 32 + lane]), x2b, t);
            #pragma unroll
            for (int off = 16; off > 0; off >>= 1)
                t += __shfl_xor_sync(FULL, t, off);
            if (n < 32) { if (lane == n) ea = t; }
            else        { if (lane == n - 32) eb = t; }
        }
    }

    float x3r[4];
    #pragma unroll
    for (int j = 0; j < 4; j++) x3r[j] = f2b[lane + 32 * j];
    #pragma unroll 2
    for (int k = 0; k < NVAR; k++) {
        float v = (k < 32) ? __shfl_sync(FULL, ea, k) : __shfl_sync(FULL, eb, k - 32);
        #pragma unroll
        for (int j = 0; j < 4; j++)
            x3r[j] = fmaf(v, __ldg(&f2w[k * 128 + lane + 32 * j]), x3r[j]);
    }
    #pragma unroll
    for (int j = 0; j < 4; j++) x3r[j] = fmaxf(x3r[j], 0.f);

    float b0 = f3b[lane], b1v = f3b[lane + 32];
    #pragma unroll 4
    for (int k = 0; k < 256; k++) {
        float v = (k < 128) ? __shfl_sync(FULL, x1r[k >> 5], k & 31)
                            : __shfl_sync(FULL, x3r[(k - 128) >> 5], (k - 128) & 31);
        b0  = fmaf(v, __ldg(&f3w[k * 64 + lane]), b0);
        b1v = fmaf(v, __ldg(&f3w[k * 64 + lane + 32]), b1v);
    }
    float x5a = fmaxf(b0, 0.f), x5b = fmaxf(b1v, 0.f);

    float c0 = f4b[lane], c1 = f4b[lane + 32];
    #pragma unroll 4
    for (int k = 0; k < 64; k++) {
        float v = (k < 32) ? __shfl_sync(FULL, x5a, k) : __shfl_sync(FULL, x5b, k - 32);
        c0 = fmaf(v, __ldg(&f4w[k * 64 + lane]), c0);
        c1 = fmaf(v, __ldg(&f4w[k * 64 + lane + 32]), c1);
    }
    float x6a = fmaxf(c0, 0.f), x6b = fmaxf(c1, 0.f);

    float d0 = f5b[lane], d1 = f5b[lane + 32];
    #pragma unroll 4
    for (int k = 0; k < 64; k++) {
        float v = (k < 32) ? __shfl_sync(FULL, x6a, k) : __shfl_sync(FULL, x6b, k - 32);
        d0 = fmaf(v, __ldg(&f5w[k * 64 + lane]), d0);
        d1 = fmaf(v, __ldg(&f5w[k * 64 + lane + 32]), d1);
    }
    float x7a = fmaxf(d0, 0.f), x7b = fmaxf(d1, 0.f);

    float l0 = ob[lane];
    float l1 = (lane < 18) ? ob[lane + 32] : 0.f;
    #pragma unroll 4
    for (int k = 0; k < 64; k++) {
        float v = (k < 32) ? __shfl_sync(FULL, x7a, k) : __shfl_sync(FULL, x7b, k - 32);
        l0 = fmaf(v, __ldg(&ow[k * NVAR + lane]), l0);
        l1 = fmaf(v, __ldg(&ow[k * NVAR + nc]), l1);
    }
    l0 = fmaxf(l0, 0.f);
    l1 = (lane < 18) ? fmaxf(l1, 0.f) : -1e30f;

    float m = fmaxf(l0, l1);
    #pragma unroll
    for (int off = 16; off > 0; off >>= 1)
        m = fmaxf(m, __shfl_xor_sync(FULL, m, off));
    float e0 = expf(l0 - m);
    float e1 = (lane < 18) ? expf(l1 - m) : 0.f;
    float ssum = e0 + e1;
    #pragma unroll
    for (int off = 16; off > 0; off >>= 1)
        ssum += __shfl_xor_sync(FULL, ssum, off);
    float inv = 1.f / ssum;
    out[s * NVAR + lane] = e0 * inv;
    if (lane < 18) out[s * NVAR + 32 + lane] = e1 * inv;
}

extern "C" void kernel_launch(void* const* d_in, const int* in_sizes, int n_in,
                              void* d_out, int out_size)
{
    (void)in_sizes; (void)n_in; (void)out_size;
    const float* x    = (const float*)d_in[0];
    const float* C    = (const float*)d_in[1];
    const float* w1   = (const float*)d_in[2];
    const float* b1   = (const float*)d_in[3];
    const float* w2   = (const float*)d_in[4];
    const float* b2   = (const float*)d_in[5];
    const float* encw = (const float*)d_in[6];
    const float* encb = (const float*)d_in[7];
    const float* f1w  = (const float*)d_in[8];
    const float* f1b  = (const float*)d_in[9];
    const float* f2w  = (const float*)d_in[10];
    const float* f2b  = (const float*)d_in[11];
    const float* f3w  = (const float*)d_in[12];
    const float* f3b  = (const float*)d_in[13];
    const float* f4w  = (const float*)d_in[14];
    const float* f4b  = (const float*)d_in[15];
    const float* f5w  = (const float*)d_in[16];
    const float* f5b  = (const float*)d_in[17];
    const float* ow   = (const float*)d_in[18];
    const float* ob   = (const float*)d_in[19];
    float* out = (float*)d_out;

    int nsm = 148;
    cudaDeviceGetAttribute(&nsm, cudaDevAttrMultiProcessorCount, 0);

    w_prep_kernel<<<94, 256>>>(w1, w2);

    cudaFuncSetAttribute(gcp_conv_kernel,
                         cudaFuncAttributeMaxDynamicSharedMemorySize, SMEM_BYTES);
    gcp_conv_kernel<<<nsm, NTHREADS, SMEM_BYTES>>>(x, b1, b2);

    gcp_mlp_kernel<<<B_SAMPLES / 8, 256>>>(C, encw, encb, f1w, f1b, f2w, f2b,
                                           f3w, f3b, f4w, f4b, f5w, f5b, ow, ob, out);
}